// round 12
// baseline (speedup 1.0000x reference)
#include <cuda_runtime.h>
#include <cuda_fp16.h>
#include <cstdint>
#include <math.h>

// Problem constants
#define BATCH 4
#define SEQ   2048
#define DIM   1024

#define BM 256           // CTA tile rows
#define BN 128           // CTA tile cols
#define KC 32            // K elements (halfs) per stage
#define THREADS 512
#define NSTAGE 2

// flags
#define F_CAUSAL_SKIP  1
#define F_CAUSAL_KLIM  2
#define F_TRANS_STORE  4
#define F_OUT_HALF     8

#define NX (BATCH * SEQ * DIM)   // 8M
#define NW (DIM * DIM)           // 1M
#define NS (BATCH * SEQ * SEQ)   // 16M

// smem: per stage [Ah 16K][Al 16K][Bh 8K][Bl 8K] = 48KB, 2 stages = 96KB
#define TILE_A_B (BM * KC * 2)   // 16384
#define TILE_B_B (BN * KC * 2)   // 8192
#define OFF_AL   TILE_A_B
#define OFF_BH   (2 * TILE_A_B)
#define OFF_BL   (2 * TILE_A_B + TILE_B_B)
#define STAGE_B  (2 * TILE_A_B + 2 * TILE_B_B)   // 49152
#define SMEM_TOTAL (NSTAGE * STAGE_B)            // 98304

// Scratch (allocation-free)
__device__ __half g_xh[NX],  g_xl[NX];
__device__ __half g_wqh[NW], g_wql[NW];
__device__ __half g_wkh[NW], g_wkl[NW];
__device__ __half g_wvh[NW], g_wvl[NW];
__device__ __half g_qh[NX],  g_ql[NX];
__device__ __half g_kh[NX],  g_kl[NX];
__device__ __half g_vth[NX], g_vtl[NX];   // V transposed [b][d][s]
__device__ float  g_s[NS];
__device__ __half g_ph[NS],  g_pl[NS];

__device__ __forceinline__ uint32_t smem_u32(const void* p) {
    uint32_t a;
    asm("{ .reg .u64 t; cvta.to.shared.u64 t, %1; cvt.u32.u64 %0, t; }" : "=r"(a) : "l"(p));
    return a;
}

#define LDMATRIX_X4(r0, r1, r2, r3, addr)                                      \
    asm volatile("ldmatrix.sync.aligned.m8n8.x4.shared.b16 {%0,%1,%2,%3}, [%4];" \
        : "=r"(r0), "=r"(r1), "=r"(r2), "=r"(r3) : "r"(addr))

#define MMA16816(d0, d1, d2, d3, a0, a1, a2, a3, b0, b1)                       \
    asm volatile("mma.sync.aligned.m16n8k16.row.col.f32.f16.f16.f32 "          \
        "{%0,%1,%2,%3},{%4,%5,%6,%7},{%8,%9},{%0,%1,%2,%3};"                   \
        : "+f"(d0), "+f"(d1), "+f"(d2), "+f"(d3)                               \
        : "r"(a0), "r"(a1), "r"(a2), "r"(a3), "r"(b0), "r"(b1))

#define CP16(dst, src) \
    asm volatile("cp.async.cg.shared.global [%0], [%1], 16;" :: "r"(dst), "l"(src))
#define CP_COMMIT()  asm volatile("cp.async.commit_group;" ::: "memory")
#define CP_WAIT1()   asm volatile("cp.async.wait_group 1;" ::: "memory")
#define CP_WAIT0()   asm volatile("cp.async.wait_group 0;" ::: "memory")

// SW64 swizzle for 64-byte rows (KC=32 halfs)
__device__ __forceinline__ uint32_t sw64(uint32_t off) {
    return off ^ ((off >> 3) & 0x30);
}

// split fp32 -> fp16 hi + fp16 residual
__device__ __forceinline__ void split1(float x, __half& h, __half& l) {
    h = __float2half_rn(x);
    l = __float2half_rn(x - __half2float(h));
}

// ---------------------------------------------------------------------------
// NT GEMM, fp16 hi/lo pre-split inputs: C = scale * (A @ B^T) + bias
// 256x128 CTA tile, 16 warps, each warp a 64x32 sub-tile.
// ---------------------------------------------------------------------------
__global__ void __launch_bounds__(THREADS, 1)
tc_gemm(const __half* __restrict__ Ah, const __half* __restrict__ Al,
        const __half* __restrict__ Bh, const __half* __restrict__ Bl,
        const float* __restrict__ bias,
        float* __restrict__ C, __half* __restrict__ Ch, __half* __restrict__ Cl,
        int K, int ldA, int ldB, int ldC, float scale, int flags,
        long long sA, long long sB, long long sC)
{
    const int bx = blockIdx.x, by = blockIdx.y, bz = blockIdx.z;
    if ((flags & F_CAUSAL_SKIP) && bx * BN >= (by + 1) * BM) return;

    extern __shared__ __align__(1024) char smem[];
    const uint32_t sbase = smem_u32(smem);

    const int tid  = threadIdx.x;
    const int lane = tid & 31;
    const int wid  = tid >> 5;
    const int wm   = wid & 3;          // 4 m-groups of 64 rows
    const int wn   = wid >> 2;         // 4 n-groups of 32 cols

    int kend = K;
    if (flags & F_CAUSAL_KLIM) kend = min(K, (by + 1) * BM);
    const int nkb = kend / KC;

    const size_t aoff = (size_t)bz * sA + (size_t)by * BM * ldA;
    const size_t boff = (size_t)bz * sB + (size_t)bx * BN * ldB;
    const __half* pAh = Ah + aoff;
    const __half* pAl = Al + aoff;
    const __half* pBh = Bh + boff;
    const __half* pBl = Bl + boff;

    // A loader: 256 rows x 4 chunks = 1024 chunks; each thread 2 chunks
    const int lrowA = tid >> 1;               // 0..255
    const int lcA   = (tid & 1) * 2;          // chunk base 0 or 2
    const uint32_t soA0 = sw64(lrowA * 64 + lcA * 16);
    const uint32_t soA1 = sw64(lrowA * 64 + lcA * 16 + 16);
    const size_t gA = (size_t)lrowA * ldA + lcA * 8;
    // B loader: 128 rows x 4 chunks = 512 chunks; each thread 1 chunk
    const int lrowB = tid >> 2;               // 0..127
    const int lcB   = tid & 3;
    const uint32_t soB0 = sw64(lrowB * 64 + lcB * 16);
    const size_t gB = (size_t)lrowB * ldB + lcB * 8;

#define LOAD_STAGE(buf, kb) do {                                               \
        const int _k0 = (kb) * KC;                                             \
        const uint32_t _sb = sbase + (buf) * STAGE_B;                          \
        CP16(_sb + soA0,          pAh + gA + _k0);                             \
        CP16(_sb + soA1,          pAh + gA + _k0 + 8);                         \
        CP16(_sb + OFF_AL + soA0, pAl + gA + _k0);                             \
        CP16(_sb + OFF_AL + soA1, pAl + gA + _k0 + 8);                         \
        CP16(_sb + OFF_BH + soB0, pBh + gB + _k0);                             \
        CP16(_sb + OFF_BL + soB0, pBl + gB + _k0);                             \
        CP_COMMIT();                                                           \
    } while (0)

    float acc[4][4][4];
#pragma unroll
    for (int i = 0; i < 4; i++)
#pragma unroll
        for (int j = 0; j < 4; j++)
#pragma unroll
            for (int c = 0; c < 4; c++) acc[i][j][c] = 0.0f;

    // ldmatrix lane-address components
    const int lr  = lane & 7;
    const int grp = lane >> 3;
    const int lm_row_off = lr + ((grp & 1) << 3);
    const int lm_col_off = (grp >> 1) << 4;

    LOAD_STAGE(0, 0);

    for (int kb = 0; kb < nkb; kb++) {
        const int buf = kb & 1;
        if (kb + 1 < nkb) {
            LOAD_STAGE(buf ^ 1, kb + 1);
            CP_WAIT1();
        } else {
            CP_WAIT0();
        }
        __syncthreads();

        const uint32_t uAh = sbase + buf * STAGE_B;
        const uint32_t uAl = uAh + OFF_AL;
        const uint32_t uBh = uAh + OFF_BH;
        const uint32_t uBl = uAh + OFF_BL;

#pragma unroll
        for (int ks = 0; ks < 2; ks++) {
            const uint32_t kbyte = ks * 32 + lm_col_off;

            uint32_t bh[2][4], bl[2][4];
#pragma unroll
            for (int ng = 0; ng < 2; ng++) {
                int nrow = wn * 32 + ng * 16 + lm_row_off;
                uint32_t off = sw64(nrow * 64 + kbyte);
                LDMATRIX_X4(bh[ng][0], bh[ng][1], bh[ng][2], bh[ng][3], uBh + off);
                LDMATRIX_X4(bl[ng][0], bl[ng][1], bl[ng][2], bl[ng][3], uBl + off);
            }

#pragma unroll
            for (int mt = 0; mt < 4; mt++) {
                int mrow = wm * 64 + mt * 16 + lm_row_off;
                uint32_t off = sw64(mrow * 64 + kbyte);
                uint32_t ah[4], al[4];
                LDMATRIX_X4(ah[0], ah[1], ah[2], ah[3], uAh + off);
                LDMATRIX_X4(al[0], al[1], al[2], al[3], uAl + off);

#pragma unroll
                for (int nt = 0; nt < 4; nt++) {
                    const int ng = nt >> 1, s = nt & 1;
                    float* d = acc[mt][nt];
                    // hi*hi + hi*lo + lo*hi  (lo*lo dropped, ~2^-22)
                    MMA16816(d[0], d[1], d[2], d[3],
                             ah[0], ah[1], ah[2], ah[3], bh[ng][s], bh[ng][s + 2]);
                    MMA16816(d[0], d[1], d[2], d[3],
                             ah[0], ah[1], ah[2], ah[3], bl[ng][s], bl[ng][s + 2]);
                    MMA16816(d[0], d[1], d[2], d[3],
                             al[0], al[1], al[2], al[3], bh[ng][s], bh[ng][s + 2]);
                }
            }
        }
        __syncthreads();
    }

    // ---- epilogue ----
    const int r0 = by * BM + wm * 64 + (lane >> 2);
    const int c0 = bx * BN + wn * 32 + ((lane & 3) << 1);

    if (!(flags & F_OUT_HALF)) {
        // fp32 output (scores / final out)
#pragma unroll
        for (int mt = 0; mt < 4; mt++) {
#pragma unroll
            for (int nt = 0; nt < 4; nt++) {
                int row = r0 + mt * 16;
                int col = c0 + nt * 8;
                float b0 = bias ? bias[col] : 0.0f;
                float b1 = bias ? bias[col + 1] : 0.0f;
                float* dst = C + (size_t)bz * sC + (size_t)row * ldC + col;
                *(float2*)dst = make_float2(acc[mt][nt][0] * scale + b0,
                                            acc[mt][nt][1] * scale + b1);
                *(float2*)(dst + 8ull * ldC) = make_float2(acc[mt][nt][2] * scale + b0,
                                                           acc[mt][nt][3] * scale + b1);
            }
        }
    } else if (!(flags & F_TRANS_STORE)) {
        // hi/lo half output, row-major (Q / K projections)
#pragma unroll
        for (int mt = 0; mt < 4; mt++) {
#pragma unroll
            for (int nt = 0; nt < 4; nt++) {
                int row = r0 + mt * 16;
                int col = c0 + nt * 8;
                float b0 = bias[col], b1 = bias[col + 1];
                float v0 = acc[mt][nt][0] * scale + b0;
                float v1 = acc[mt][nt][1] * scale + b1;
                float v2 = acc[mt][nt][2] * scale + b0;
                float v3 = acc[mt][nt][3] * scale + b1;
                __half h0, h1, h2, h3, l0, l1, l2, l3;
                split1(v0, h0, l0); split1(v1, h1, l1);
                split1(v2, h2, l2); split1(v3, h3, l3);
                size_t o0 = (size_t)bz * sC + (size_t)row * ldC + col;
                size_t o1 = o0 + 8ull * ldC;
                *(__half2*)(Ch + o0) = __halves2half2(h0, h1);
                *(__half2*)(Cl + o0) = __halves2half2(l0, l1);
                *(__half2*)(Ch + o1) = __halves2half2(h2, h3);
                *(__half2*)(Cl + o1) = __halves2half2(l2, l3);
            }
        }
    } else {
        // hi/lo half output, transposed (V projection -> [b][d][s])
#pragma unroll
        for (int mt = 0; mt < 4; mt++) {
            int row = r0 + mt * 16;
            int b = row >> 11;
            int s = row & (SEQ - 1);
            __half* dh = g_vth + (size_t)b * DIM * SEQ + s;
            __half* dl = g_vtl + (size_t)b * DIM * SEQ + s;
#pragma unroll
            for (int nt = 0; nt < 4; nt++) {
                int col = c0 + nt * 8;
                float b0 = bias[col], b1 = bias[col + 1];
                __half h, l;
                split1(acc[mt][nt][0] * scale + b0, h, l);
                dh[(size_t)col * SEQ] = h;       dl[(size_t)col * SEQ] = l;
                split1(acc[mt][nt][1] * scale + b1, h, l);
                dh[(size_t)(col + 1) * SEQ] = h; dl[(size_t)(col + 1) * SEQ] = l;
                split1(acc[mt][nt][2] * scale + b0, h, l);
                dh[(size_t)col * SEQ + 8] = h;   dl[(size_t)col * SEQ + 8] = l;
                split1(acc[mt][nt][3] * scale + b1, h, l);
                dh[(size_t)(col + 1) * SEQ + 8] = h; dl[(size_t)(col + 1) * SEQ + 8] = l;
            }
        }
    }
#undef LOAD_STAGE
}

// ---------------------------------------------------------------------------
// elementwise fp32 -> (hi, lo) fp16 split, float4-vectorized
// ---------------------------------------------------------------------------
__global__ void __launch_bounds__(256)
split_f32(const float* __restrict__ x, __half* __restrict__ h,
          __half* __restrict__ l, int n4)
{
    int i = blockIdx.x * blockDim.x + threadIdx.x;
    if (i >= n4) return;
    float4 v = ((const float4*)x)[i];
    __half hx = __float2half_rn(v.x), hy = __float2half_rn(v.y);
    __half hz = __float2half_rn(v.z), hw = __float2half_rn(v.w);
    __half2 H0 = __halves2half2(hx, hy), H1 = __halves2half2(hz, hw);
    __half2 L0 = __floats2half2_rn(v.x - __half2float(hx), v.y - __half2float(hy));
    __half2 L1 = __floats2half2_rn(v.z - __half2float(hz), v.w - __half2float(hw));
    ((__half2*)h)[i * 2]     = H0;
    ((__half2*)h)[i * 2 + 1] = H1;
    ((__half2*)l)[i * 2]     = L0;
    ((__half2*)l)[i * 2 + 1] = L1;
}

// ---------------------------------------------------------------------------
// Causal row softmax: fp32 scores -> hi/lo fp16 probabilities (zero tails)
// ---------------------------------------------------------------------------
__global__ void __launch_bounds__(256)
causal_softmax(const float* __restrict__ S, __half* __restrict__ Ph,
               __half* __restrict__ Pl, int seq)
{
    int r = blockIdx.x;
    int b = blockIdx.y;
    size_t base = ((size_t)b * seq + (size_t)r) * seq;
    const float* row = S + base;
    int n = r + 1;
    int tid = threadIdx.x;

    __shared__ float red[256];

    float m = -1e30f;
    for (int j = tid; j < n; j += 256) m = fmaxf(m, row[j]);
    red[tid] = m; __syncthreads();
    for (int s = 128; s > 0; s >>= 1) {
        if (tid < s) red[tid] = fmaxf(red[tid], red[tid + s]);
        __syncthreads();
    }
    m = red[0]; __syncthreads();

    float ev[8];
    int cnt = 0;
    float sum = 0.0f;
    for (int j = tid; j < n; j += 256) {
        float e = __expf(row[j] - m);
        ev[cnt++] = e;
        sum += e;
    }
    red[tid] = sum; __syncthreads();
    for (int s = 128; s > 0; s >>= 1) {
        if (tid < s) red[tid] += red[tid + s];
        __syncthreads();
    }
    float inv = 1.0f / red[0];

    cnt = 0;
    for (int j = tid; j < n; j += 256) {
        float p = ev[cnt++] * inv;
        __half h = __float2half_rn(p);
        Ph[base + j] = h;
        Pl[base + j] = __float2half_rn(p - __half2float(h));
    }
    __half z = __float2half_rn(0.0f);
    for (int j = n + tid; j < seq; j += 256) {
        Ph[base + j] = z;
        Pl[base + j] = z;
    }
}

// ---------------------------------------------------------------------------
extern "C" void kernel_launch(void* const* d_in, const int* in_sizes, int n_in,
                              void* d_out, int out_size)
{
    const float* X  = (const float*)d_in[0];
    const float* Wq = (const float*)d_in[1];
    const float* bq = (const float*)d_in[2];
    const float* Wk = (const float*)d_in[3];
    const float* bk = (const float*)d_in[4];
    const float* Wv = (const float*)d_in[5];
    const float* bv = (const float*)d_in[6];
    float* out = (float*)d_out;

    __half *xh, *xl, *wqh, *wql, *wkh, *wkl, *wvh, *wvl;
    __half *qh, *ql, *kh, *kl, *vth, *vtl, *ph, *pl;
    float* sp;
    cudaGetSymbolAddress((void**)&xh,  g_xh);  cudaGetSymbolAddress((void**)&xl,  g_xl);
    cudaGetSymbolAddress((void**)&wqh, g_wqh); cudaGetSymbolAddress((void**)&wql, g_wql);
    cudaGetSymbolAddress((void**)&wkh, g_wkh); cudaGetSymbolAddress((void**)&wkl, g_wkl);
    cudaGetSymbolAddress((void**)&wvh, g_wvh); cudaGetSymbolAddress((void**)&wvl, g_wvl);
    cudaGetSymbolAddress((void**)&qh,  g_qh);  cudaGetSymbolAddress((void**)&ql,  g_ql);
    cudaGetSymbolAddress((void**)&kh,  g_kh);  cudaGetSymbolAddress((void**)&kl,  g_kl);
    cudaGetSymbolAddress((void**)&vth, g_vth); cudaGetSymbolAddress((void**)&vtl, g_vtl);
    cudaGetSymbolAddress((void**)&ph,  g_ph);  cudaGetSymbolAddress((void**)&pl,  g_pl);
    cudaGetSymbolAddress((void**)&sp,  g_s);

    static int smem_set = 0;
    if (!smem_set) {
        cudaFuncSetAttribute(tc_gemm, cudaFuncAttributeMaxDynamicSharedMemorySize, SMEM_TOTAL);
        smem_set = 1;
    }

    const int M = BATCH * SEQ;                       // 8192
    const long long sQK = (long long)SEQ * DIM;
    const long long sVT = (long long)DIM * SEQ;
    const long long sSS = (long long)SEQ * SEQ;

    // 0) pre-split inputs into hi/lo fp16
    split_f32<<<(NX / 4 + 255) / 256, 256>>>(X,  xh,  xl,  NX / 4);
    split_f32<<<(NW / 4 + 255) / 256, 256>>>(Wq, wqh, wql, NW / 4);
    split_f32<<<(NW / 4 + 255) / 256, 256>>>(Wk, wkh, wkl, NW / 4);
    split_f32<<<(NW / 4 + 255) / 256, 256>>>(Wv, wvh, wvl, NW / 4);

    // 1) QKV projections (output hi/lo fp16; V transposed)
    {
        dim3 grid(DIM / BN, M / BM, 1);
        tc_gemm<<<grid, THREADS, SMEM_TOTAL>>>(xh, xl, wqh, wql, bq, nullptr, qh, ql,
                                               DIM, DIM, DIM, DIM, 1.0f, F_OUT_HALF, 0, 0, 0);
        tc_gemm<<<grid, THREADS, SMEM_TOTAL>>>(xh, xl, wkh, wkl, bk, nullptr, kh, kl,
                                               DIM, DIM, DIM, DIM, 1.0f, F_OUT_HALF, 0, 0, 0);
        tc_gemm<<<grid, THREADS, SMEM_TOTAL>>>(xh, xl, wvh, wvl, bv, nullptr, vth, vtl,
                                               DIM, DIM, DIM, DIM, 1.0f,
                                               F_OUT_HALF | F_TRANS_STORE, 0, 0, 0);
    }

    // 2) scores = (Q @ K^T) / 32, fp32, causal tiles only
    {
        dim3 grid(SEQ / BN, SEQ / BM, BATCH);
        tc_gemm<<<grid, THREADS, SMEM_TOTAL>>>(qh, ql, kh, kl, nullptr, sp, nullptr, nullptr,
                                               DIM, DIM, DIM, SEQ, 0.03125f,
                                               F_CAUSAL_SKIP, sQK, sQK, sSS);
    }

    // 3) causal softmax -> hi/lo fp16 P
    {
        dim3 grid(SEQ, BATCH);
        causal_softmax<<<grid, 256>>>(sp, ph, pl, SEQ);
    }

    // 4) out = P @ Vt^T  (fp32 out; K limited to causal boundary)
    {
        dim3 grid(DIM / BN, SEQ / BM, BATCH);
        tc_gemm<<<grid, THREADS, SMEM_TOTAL>>>(ph, pl, vth, vtl, nullptr, out, nullptr, nullptr,
                                               SEQ, SEQ, SEQ, DIM, 1.0f,
                                               F_CAUSAL_KLIM, sSS, sVT, sQK);
    }
}

// round 13
// speedup vs baseline: 1.1077x; 1.1077x over previous
#include <cuda_runtime.h>
#include <cuda_fp16.h>
#include <cstdint>
#include <math.h>

// Problem constants
#define BATCH 4
#define SEQ   2048
#define DIM   1024

#define BM 128
#define BN 128
#define KC 64            // K elements (halfs) per stage (128B rows, SW128)
#define THREADS 512
#define NSTAGE 2

// flags
#define F_CAUSAL_SKIP  1
#define F_CAUSAL_KLIM  2
#define F_TRANS_STORE  4
#define F_OUT_HALF     8

#define NX (BATCH * SEQ * DIM)   // 8M
#define NW (DIM * DIM)           // 1M
#define NS (BATCH * SEQ * SEQ)   // 16M

// smem: 4 tiles (Ah,Al,Bh,Bl) x 16KB = 64KB per stage, 2 stages = 128KB
#define TILE_B  (BM * KC * 2)    // 16384
#define STAGE_B (4 * TILE_B)     // 65536
#define SMEM_TOTAL (NSTAGE * STAGE_B)   // 131072

// Scratch (allocation-free)
__device__ __half g_xh[NX],  g_xl[NX];
__device__ __half g_wqh[NW], g_wql[NW];
__device__ __half g_wkh[NW], g_wkl[NW];
__device__ __half g_wvh[NW], g_wvl[NW];
__device__ __half g_qh[NX],  g_ql[NX];
__device__ __half g_kh[NX],  g_kl[NX];
__device__ __half g_vth[NX], g_vtl[NX];   // V transposed [b][d][s]
__device__ float  g_s[NS];
__device__ __half g_ph[NS],  g_pl[NS];

__device__ __forceinline__ uint32_t smem_u32(const void* p) {
    uint32_t a;
    asm("{ .reg .u64 t; cvta.to.shared.u64 t, %1; cvt.u32.u64 %0, t; }" : "=r"(a) : "l"(p));
    return a;
}

#define LDMATRIX_X4(r0, r1, r2, r3, addr)                                      \
    asm volatile("ldmatrix.sync.aligned.m8n8.x4.shared.b16 {%0,%1,%2,%3}, [%4];" \
        : "=r"(r0), "=r"(r1), "=r"(r2), "=r"(r3) : "r"(addr))

#define MMA16816(d0, d1, d2, d3, a0, a1, a2, a3, b0, b1)                       \
    asm volatile("mma.sync.aligned.m16n8k16.row.col.f32.f16.f16.f32 "          \
        "{%0,%1,%2,%3},{%4,%5,%6,%7},{%8,%9},{%0,%1,%2,%3};"                   \
        : "+f"(d0), "+f"(d1), "+f"(d2), "+f"(d3)                               \
        : "r"(a0), "r"(a1), "r"(a2), "r"(a3), "r"(b0), "r"(b1))

#define CP16(dst, src) \
    asm volatile("cp.async.cg.shared.global [%0], [%1], 16;" :: "r"(dst), "l"(src))
#define CP_COMMIT()  asm volatile("cp.async.commit_group;" ::: "memory")
#define CP_WAIT1()   asm volatile("cp.async.wait_group 1;" ::: "memory")
#define CP_WAIT0()   asm volatile("cp.async.wait_group 0;" ::: "memory")

// SW128 swizzle for 128-byte rows (KC=64 halfs)
__device__ __forceinline__ uint32_t sw128(uint32_t off) {
    return off ^ ((off >> 3) & 0x70);
}

// split fp32 -> fp16 hi + fp16 residual
__device__ __forceinline__ void split1(float x, __half& h, __half& l) {
    h = __float2half_rn(x);
    l = __float2half_rn(x - __half2float(h));
}

// ---------------------------------------------------------------------------
// NT GEMM, fp16 hi/lo pre-split inputs: C = scale * (A @ B^T) + bias
// 128x128 CTA tile, 16 warps (32x32 warp tile), KC=64 stages.
// ---------------------------------------------------------------------------
__global__ void __launch_bounds__(THREADS, 1)
tc_gemm(const __half* __restrict__ Ah, const __half* __restrict__ Al,
        const __half* __restrict__ Bh, const __half* __restrict__ Bl,
        const float* __restrict__ bias,
        float* __restrict__ C, __half* __restrict__ Ch, __half* __restrict__ Cl,
        int K, int ldA, int ldB, int ldC, float scale, int flags,
        long long sA, long long sB, long long sC)
{
    const int bx = blockIdx.x, by = blockIdx.y, bz = blockIdx.z;
    if ((flags & F_CAUSAL_SKIP) && bx > by) return;

    extern __shared__ __align__(1024) char smem[];
    const uint32_t sbase = smem_u32(smem);

    const int tid  = threadIdx.x;
    const int lane = tid & 31;
    const int wid  = tid >> 5;
    const int wm   = wid & 3;          // 4 m-groups of 32 rows
    const int wn   = wid >> 2;         // 4 n-groups of 32 cols

    int kend = K;
    if (flags & F_CAUSAL_KLIM) kend = min(K, (by + 1) * BM);
    const int nkb = kend / KC;

    const size_t aoff = (size_t)bz * sA + (size_t)by * BM * ldA;
    const size_t boff = (size_t)bz * sB + (size_t)bx * BN * ldB;
    const __half* pAh = Ah + aoff;
    const __half* pAl = Al + aoff;
    const __half* pBh = Bh + boff;
    const __half* pBl = Bl + boff;

    // loader coords: 128 rows x 8 chunks = 1024 chunks per tile; 2 per thread
    const int lrow = tid >> 2;                // 0..127
    const int lc   = (tid & 3) * 2;           // chunk base 0,2,4,6
    const uint32_t so0 = sw128(lrow * 128 + lc * 16);
    const uint32_t so1 = sw128(lrow * 128 + lc * 16 + 16);
    const size_t gA = (size_t)lrow * ldA + lc * 8;
    const size_t gB = (size_t)lrow * ldB + lc * 8;

#define LOAD_STAGE(buf, kb) do {                                               \
        const int _k0 = (kb) * KC;                                             \
        const uint32_t _sb = sbase + (buf) * STAGE_B;                          \
        CP16(_sb + so0,              pAh + gA + _k0);                          \
        CP16(_sb + so1,              pAh + gA + _k0 + 8);                      \
        CP16(_sb + TILE_B + so0,     pAl + gA + _k0);                          \
        CP16(_sb + TILE_B + so1,     pAl + gA + _k0 + 8);                      \
        CP16(_sb + 2*TILE_B + so0,   pBh + gB + _k0);                          \
        CP16(_sb + 2*TILE_B + so1,   pBh + gB + _k0 + 8);                      \
        CP16(_sb + 3*TILE_B + so0,   pBl + gB + _k0);                          \
        CP16(_sb + 3*TILE_B + so1,   pBl + gB + _k0 + 8);                      \
        CP_COMMIT();                                                           \
    } while (0)

    float acc[2][4][4];
#pragma unroll
    for (int i = 0; i < 2; i++)
#pragma unroll
        for (int j = 0; j < 4; j++)
#pragma unroll
            for (int c = 0; c < 4; c++) acc[i][j][c] = 0.0f;

    // ldmatrix lane-address components
    const int lr  = lane & 7;
    const int grp = lane >> 3;
    const int lm_row_off = lr + ((grp & 1) << 3);
    const int lm_col_off = (grp >> 1) << 4;

    LOAD_STAGE(0, 0);

    for (int kb = 0; kb < nkb; kb++) {
        const int buf = kb & 1;
        if (kb + 1 < nkb) {
            LOAD_STAGE(buf ^ 1, kb + 1);
            CP_WAIT1();
        } else {
            CP_WAIT0();
        }
        __syncthreads();

        const uint32_t uAh = sbase + buf * STAGE_B;
        const uint32_t uAl = uAh + TILE_B;
        const uint32_t uBh = uAh + 2 * TILE_B;
        const uint32_t uBl = uAh + 3 * TILE_B;

#pragma unroll
        for (int ks = 0; ks < 4; ks++) {
            const uint32_t kbyte = ks * 32 + lm_col_off;

            uint32_t bh[2][4], bl[2][4];
#pragma unroll
            for (int ng = 0; ng < 2; ng++) {
                int nrow = wn * 32 + ng * 16 + lm_row_off;
                uint32_t off = sw128(nrow * 128 + kbyte);
                LDMATRIX_X4(bh[ng][0], bh[ng][1], bh[ng][2], bh[ng][3], uBh + off);
                LDMATRIX_X4(bl[ng][0], bl[ng][1], bl[ng][2], bl[ng][3], uBl + off);
            }

#pragma unroll
            for (int mt = 0; mt < 2; mt++) {
                int mrow = wm * 32 + mt * 16 + lm_row_off;
                uint32_t off = sw128(mrow * 128 + kbyte);
                uint32_t ah[4], al[4];
                LDMATRIX_X4(ah[0], ah[1], ah[2], ah[3], uAh + off);
                LDMATRIX_X4(al[0], al[1], al[2], al[3], uAl + off);

#pragma unroll
                for (int nt = 0; nt < 4; nt++) {
                    const int ng = nt >> 1, s = nt & 1;
                    float* d = acc[mt][nt];
                    // hi*hi + hi*lo + lo*hi  (lo*lo dropped, ~2^-22)
                    MMA16816(d[0], d[1], d[2], d[3],
                             ah[0], ah[1], ah[2], ah[3], bh[ng][s], bh[ng][s + 2]);
                    MMA16816(d[0], d[1], d[2], d[3],
                             ah[0], ah[1], ah[2], ah[3], bl[ng][s], bl[ng][s + 2]);
                    MMA16816(d[0], d[1], d[2], d[3],
                             al[0], al[1], al[2], al[3], bh[ng][s], bh[ng][s + 2]);
                }
            }
        }
        __syncthreads();
    }

    // ---- epilogue ----
    const int r0 = by * BM + wm * 32 + (lane >> 2);
    const int c0 = bx * BN + wn * 32 + ((lane & 3) << 1);

    if (!(flags & F_OUT_HALF)) {
        // fp32 output (scores / final out)
#pragma unroll
        for (int mt = 0; mt < 2; mt++) {
#pragma unroll
            for (int nt = 0; nt < 4; nt++) {
                int row = r0 + mt * 16;
                int col = c0 + nt * 8;
                float b0 = bias ? bias[col] : 0.0f;
                float b1 = bias ? bias[col + 1] : 0.0f;
                float* dst = C + (size_t)bz * sC + (size_t)row * ldC + col;
                *(float2*)dst = make_float2(acc[mt][nt][0] * scale + b0,
                                            acc[mt][nt][1] * scale + b1);
                *(float2*)(dst + 8ull * ldC) = make_float2(acc[mt][nt][2] * scale + b0,
                                                           acc[mt][nt][3] * scale + b1);
            }
        }
    } else if (!(flags & F_TRANS_STORE)) {
        // hi/lo half output, row-major (Q / K projections)
#pragma unroll
        for (int mt = 0; mt < 2; mt++) {
#pragma unroll
            for (int nt = 0; nt < 4; nt++) {
                int row = r0 + mt * 16;
                int col = c0 + nt * 8;
                float b0 = bias[col], b1 = bias[col + 1];
                float v0 = acc[mt][nt][0] * scale + b0;
                float v1 = acc[mt][nt][1] * scale + b1;
                float v2 = acc[mt][nt][2] * scale + b0;
                float v3 = acc[mt][nt][3] * scale + b1;
                __half h0, h1, h2, h3, l0, l1, l2, l3;
                split1(v0, h0, l0); split1(v1, h1, l1);
                split1(v2, h2, l2); split1(v3, h3, l3);
                size_t o0 = (size_t)bz * sC + (size_t)row * ldC + col;
                size_t o1 = o0 + 8ull * ldC;
                *(__half2*)(Ch + o0) = __halves2half2(h0, h1);
                *(__half2*)(Cl + o0) = __halves2half2(l0, l1);
                *(__half2*)(Ch + o1) = __halves2half2(h2, h3);
                *(__half2*)(Cl + o1) = __halves2half2(l2, l3);
            }
        }
    } else {
        // hi/lo half output, transposed (V projection -> [b][d][s])
#pragma unroll
        for (int mt = 0; mt < 2; mt++) {
            int row = r0 + mt * 16;
            int b = row >> 11;
            int s = row & (SEQ - 1);
            __half* dh = g_vth + (size_t)b * DIM * SEQ + s;
            __half* dl = g_vtl + (size_t)b * DIM * SEQ + s;
#pragma unroll
            for (int nt = 0; nt < 4; nt++) {
                int col = c0 + nt * 8;
                float b0 = bias[col], b1 = bias[col + 1];
                __half h, l;
                split1(acc[mt][nt][0] * scale + b0, h, l);
                dh[(size_t)col * SEQ] = h;       dl[(size_t)col * SEQ] = l;
                split1(acc[mt][nt][1] * scale + b1, h, l);
                dh[(size_t)(col + 1) * SEQ] = h; dl[(size_t)(col + 1) * SEQ] = l;
                split1(acc[mt][nt][2] * scale + b0, h, l);
                dh[(size_t)col * SEQ + 8] = h;   dl[(size_t)col * SEQ + 8] = l;
                split1(acc[mt][nt][3] * scale + b1, h, l);
                dh[(size_t)(col + 1) * SEQ + 8] = h; dl[(size_t)(col + 1) * SEQ + 8] = l;
            }
        }
    }
#undef LOAD_STAGE
}

// ---------------------------------------------------------------------------
// elementwise fp32 -> (hi, lo) fp16 split, float4-vectorized
// ---------------------------------------------------------------------------
__global__ void __launch_bounds__(256)
split_f32(const float* __restrict__ x, __half* __restrict__ h,
          __half* __restrict__ l, int n4)
{
    int i = blockIdx.x * blockDim.x + threadIdx.x;
    if (i >= n4) return;
    float4 v = ((const float4*)x)[i];
    __half hx = __float2half_rn(v.x), hy = __float2half_rn(v.y);
    __half hz = __float2half_rn(v.z), hw = __float2half_rn(v.w);
    __half2 H0 = __halves2half2(hx, hy), H1 = __halves2half2(hz, hw);
    __half2 L0 = __floats2half2_rn(v.x - __half2float(hx), v.y - __half2float(hy));
    __half2 L1 = __floats2half2_rn(v.z - __half2float(hz), v.w - __half2float(hw));
    ((__half2*)h)[i * 2]     = H0;
    ((__half2*)h)[i * 2 + 1] = H1;
    ((__half2*)l)[i * 2]     = L0;
    ((__half2*)l)[i * 2 + 1] = L1;
}

// ---------------------------------------------------------------------------
// Causal row softmax: fp32 scores -> hi/lo fp16 probabilities (zero tails)
// ---------------------------------------------------------------------------
__global__ void __launch_bounds__(256)
causal_softmax(const float* __restrict__ S, __half* __restrict__ Ph,
               __half* __restrict__ Pl, int seq)
{
    int r = blockIdx.x;
    int b = blockIdx.y;
    size_t base = ((size_t)b * seq + (size_t)r) * seq;
    const float* row = S + base;
    int n = r + 1;
    int tid = threadIdx.x;

    __shared__ float red[256];

    float m = -1e30f;
    for (int j = tid; j < n; j += 256) m = fmaxf(m, row[j]);
    red[tid] = m; __syncthreads();
    for (int s = 128; s > 0; s >>= 1) {
        if (tid < s) red[tid] = fmaxf(red[tid], red[tid + s]);
        __syncthreads();
    }
    m = red[0]; __syncthreads();

    float ev[8];
    int cnt = 0;
    float sum = 0.0f;
    for (int j = tid; j < n; j += 256) {
        float e = __expf(row[j] - m);
        ev[cnt++] = e;
        sum += e;
    }
    red[tid] = sum; __syncthreads();
    for (int s = 128; s > 0; s >>= 1) {
        if (tid < s) red[tid] += red[tid + s];
        __syncthreads();
    }
    float inv = 1.0f / red[0];

    cnt = 0;
    for (int j = tid; j < n; j += 256) {
        float p = ev[cnt++] * inv;
        __half h = __float2half_rn(p);
        Ph[base + j] = h;
        Pl[base + j] = __float2half_rn(p - __half2float(h));
    }
    __half z = __float2half_rn(0.0f);
    for (int j = n + tid; j < seq; j += 256) {
        Ph[base + j] = z;
        Pl[base + j] = z;
    }
}

// ---------------------------------------------------------------------------
extern "C" void kernel_launch(void* const* d_in, const int* in_sizes, int n_in,
                              void* d_out, int out_size)
{
    const float* X  = (const float*)d_in[0];
    const float* Wq = (const float*)d_in[1];
    const float* bq = (const float*)d_in[2];
    const float* Wk = (const float*)d_in[3];
    const float* bk = (const float*)d_in[4];
    const float* Wv = (const float*)d_in[5];
    const float* bv = (const float*)d_in[6];
    float* out = (float*)d_out;

    __half *xh, *xl, *wqh, *wql, *wkh, *wkl, *wvh, *wvl;
    __half *qh, *ql, *kh, *kl, *vth, *vtl, *ph, *pl;
    float* sp;
    cudaGetSymbolAddress((void**)&xh,  g_xh);  cudaGetSymbolAddress((void**)&xl,  g_xl);
    cudaGetSymbolAddress((void**)&wqh, g_wqh); cudaGetSymbolAddress((void**)&wql, g_wql);
    cudaGetSymbolAddress((void**)&wkh, g_wkh); cudaGetSymbolAddress((void**)&wkl, g_wkl);
    cudaGetSymbolAddress((void**)&wvh, g_wvh); cudaGetSymbolAddress((void**)&wvl, g_wvl);
    cudaGetSymbolAddress((void**)&qh,  g_qh);  cudaGetSymbolAddress((void**)&ql,  g_ql);
    cudaGetSymbolAddress((void**)&kh,  g_kh);  cudaGetSymbolAddress((void**)&kl,  g_kl);
    cudaGetSymbolAddress((void**)&vth, g_vth); cudaGetSymbolAddress((void**)&vtl, g_vtl);
    cudaGetSymbolAddress((void**)&ph,  g_ph);  cudaGetSymbolAddress((void**)&pl,  g_pl);
    cudaGetSymbolAddress((void**)&sp,  g_s);

    static int smem_set = 0;
    if (!smem_set) {
        cudaFuncSetAttribute(tc_gemm, cudaFuncAttributeMaxDynamicSharedMemorySize, SMEM_TOTAL);
        smem_set = 1;
    }

    const int M = BATCH * SEQ;                       // 8192
    const long long sQK = (long long)SEQ * DIM;
    const long long sVT = (long long)DIM * SEQ;
    const long long sSS = (long long)SEQ * SEQ;

    // 0) pre-split inputs into hi/lo fp16
    split_f32<<<(NX / 4 + 255) / 256, 256>>>(X,  xh,  xl,  NX / 4);
    split_f32<<<(NW / 4 + 255) / 256, 256>>>(Wq, wqh, wql, NW / 4);
    split_f32<<<(NW / 4 + 255) / 256, 256>>>(Wk, wkh, wkl, NW / 4);
    split_f32<<<(NW / 4 + 255) / 256, 256>>>(Wv, wvh, wvl, NW / 4);

    // 1) QKV projections (output hi/lo fp16; V transposed)
    {
        dim3 grid(DIM / BN, M / BM, 1);
        tc_gemm<<<grid, THREADS, SMEM_TOTAL>>>(xh, xl, wqh, wql, bq, nullptr, qh, ql,
                                               DIM, DIM, DIM, DIM, 1.0f, F_OUT_HALF, 0, 0, 0);
        tc_gemm<<<grid, THREADS, SMEM_TOTAL>>>(xh, xl, wkh, wkl, bk, nullptr, kh, kl,
                                               DIM, DIM, DIM, DIM, 1.0f, F_OUT_HALF, 0, 0, 0);
        tc_gemm<<<grid, THREADS, SMEM_TOTAL>>>(xh, xl, wvh, wvl, bv, nullptr, vth, vtl,
                                               DIM, DIM, DIM, DIM, 1.0f,
                                               F_OUT_HALF | F_TRANS_STORE, 0, 0, 0);
    }

    // 2) scores = (Q @ K^T) / 32, fp32, causal tiles only
    {
        dim3 grid(SEQ / BN, SEQ / BM, BATCH);
        tc_gemm<<<grid, THREADS, SMEM_TOTAL>>>(qh, ql, kh, kl, nullptr, sp, nullptr, nullptr,
                                               DIM, DIM, DIM, SEQ, 0.03125f,
                                               F_CAUSAL_SKIP, sQK, sQK, sSS);
    }

    // 3) causal softmax -> hi/lo fp16 P
    {
        dim3 grid(SEQ, BATCH);
        causal_softmax<<<grid, 256>>>(sp, ph, pl, SEQ);
    }

    // 4) out = P @ Vt^T  (fp32 out; K limited to causal boundary)
    {
        dim3 grid(DIM / BN, SEQ / BM, BATCH);
        tc_gemm<<<grid, THREADS, SMEM_TOTAL>>>(ph, pl, vth, vtl, nullptr, out, nullptr, nullptr,
                                               SEQ, SEQ, SEQ, DIM, 1.0f,
                                               F_CAUSAL_KLIM, sSS, sVT, sQK);
    }
}

// round 14
// speedup vs baseline: 1.2311x; 1.1114x over previous
#include <cuda_runtime.h>
#include <cuda_fp16.h>
#include <cstdint>
#include <math.h>

// Problem constants
#define BATCH 4
#define SEQ   2048
#define DIM   1024

#define BM 128
#define BN 128
#define KC 64            // K elements (halfs) per stage (128B rows, SW128)
#define THREADS 512
#define NSTAGE 2

// flags
#define F_CAUSAL_SKIP  1
#define F_CAUSAL_KLIM  2
#define F_TWO_TERM     16
#define F_REV_Y        32

#define NX (BATCH * SEQ * DIM)   // 8M
#define NW (DIM * DIM)           // 1M
#define NS (BATCH * SEQ * SEQ)   // 16M

// smem: 4 tiles (Ah,Al,Bh,Bl) x 16KB = 64KB per stage, 2 stages = 128KB
#define TILE_B  (BM * KC * 2)    // 16384
#define STAGE_B (4 * TILE_B)     // 65536
#define SMEM_TOTAL (NSTAGE * STAGE_B)   // 131072

// Scratch (allocation-free)
__device__ __half g_xh[NX],  g_xl[NX];
__device__ __half g_wqh[NW], g_wql[NW];
__device__ __half g_wkh[NW], g_wkl[NW];
__device__ __half g_wvh[NW], g_wvl[NW];
__device__ __half g_qh[NX],  g_ql[NX];
__device__ __half g_kh[NX],  g_kl[NX];
__device__ __half g_vth[NX], g_vtl[NX];   // V transposed [b][d][s]
__device__ float  g_s[NS];
__device__ __half g_ph[NS],  g_pl[NS];

__device__ __forceinline__ uint32_t smem_u32(const void* p) {
    uint32_t a;
    asm("{ .reg .u64 t; cvta.to.shared.u64 t, %1; cvt.u32.u64 %0, t; }" : "=r"(a) : "l"(p));
    return a;
}

#define LDMATRIX_X4(r0, r1, r2, r3, addr)                                      \
    asm volatile("ldmatrix.sync.aligned.m8n8.x4.shared.b16 {%0,%1,%2,%3}, [%4];" \
        : "=r"(r0), "=r"(r1), "=r"(r2), "=r"(r3) : "r"(addr))

#define MMA16816(d0, d1, d2, d3, a0, a1, a2, a3, b0, b1)                       \
    asm volatile("mma.sync.aligned.m16n8k16.row.col.f32.f16.f16.f32 "          \
        "{%0,%1,%2,%3},{%4,%5,%6,%7},{%8,%9},{%0,%1,%2,%3};"                   \
        : "+f"(d0), "+f"(d1), "+f"(d2), "+f"(d3)                               \
        : "r"(a0), "r"(a1), "r"(a2), "r"(a3), "r"(b0), "r"(b1))

#define CP16(dst, src) \
    asm volatile("cp.async.cg.shared.global [%0], [%1], 16;" :: "r"(dst), "l"(src))
#define CP_COMMIT()  asm volatile("cp.async.commit_group;" ::: "memory")
#define CP_WAIT1()   asm volatile("cp.async.wait_group 1;" ::: "memory")
#define CP_WAIT0()   asm volatile("cp.async.wait_group 0;" ::: "memory")

// SW128 swizzle for 128-byte rows (KC=64 halfs)
__device__ __forceinline__ uint32_t sw128(uint32_t off) {
    return off ^ ((off >> 3) & 0x70);
}

// split fp32 -> fp16 hi + fp16 residual
__device__ __forceinline__ void split1(float x, __half& h, __half& l) {
    h = __float2half_rn(x);
    l = __float2half_rn(x - __half2float(h));
}

// ---------------------------------------------------------------------------
// Shared mainloop body (macro so both kernels inline it identically).
// Requires in scope: sbase, pAh,pAl,pBh,pBl, gA,gB, so0,so1, nkb, acc,
// lm_row_off, lm_col_off, wm, wn, ldA, ldB, two_term.
// ---------------------------------------------------------------------------
#define GEMM_MAINLOOP()                                                        \
    LOAD_STAGE(0, 0);                                                          \
    for (int kb = 0; kb < nkb; kb++) {                                         \
        const int buf = kb & 1;                                                \
        if (kb + 1 < nkb) { LOAD_STAGE(buf ^ 1, kb + 1); CP_WAIT1(); }         \
        else             { CP_WAIT0(); }                                       \
        __syncthreads();                                                       \
        const uint32_t uAh = sbase + buf * STAGE_B;                            \
        const uint32_t uAl = uAh + TILE_B;                                     \
        const uint32_t uBh = uAh + 2 * TILE_B;                                 \
        const uint32_t uBl = uAh + 3 * TILE_B;                                 \
        _Pragma("unroll")                                                      \
        for (int ks = 0; ks < 4; ks++) {                                       \
            const uint32_t kbyte = ks * 32 + lm_col_off;                       \
            uint32_t bh[2][4], bl[2][4];                                       \
            _Pragma("unroll")                                                  \
            for (int ng = 0; ng < 2; ng++) {                                   \
                int nrow = wn * 32 + ng * 16 + lm_row_off;                     \
                uint32_t off = sw128(nrow * 128 + kbyte);                      \
                LDMATRIX_X4(bh[ng][0], bh[ng][1], bh[ng][2], bh[ng][3], uBh + off); \
                LDMATRIX_X4(bl[ng][0], bl[ng][1], bl[ng][2], bl[ng][3], uBl + off); \
            }                                                                  \
            _Pragma("unroll")                                                  \
            for (int mt = 0; mt < 2; mt++) {                                   \
                int mrow = wm * 32 + mt * 16 + lm_row_off;                     \
                uint32_t off = sw128(mrow * 128 + kbyte);                      \
                uint32_t ah[4], al[4];                                         \
                LDMATRIX_X4(ah[0], ah[1], ah[2], ah[3], uAh + off);            \
                LDMATRIX_X4(al[0], al[1], al[2], al[3], uAl + off);            \
                _Pragma("unroll")                                              \
                for (int nt = 0; nt < 4; nt++) {                               \
                    const int ng = nt >> 1, s = nt & 1;                        \
                    float* d = acc[mt][nt];                                    \
                    MMA16816(d[0], d[1], d[2], d[3],                           \
                             ah[0], ah[1], ah[2], ah[3], bh[ng][s], bh[ng][s + 2]); \
                    MMA16816(d[0], d[1], d[2], d[3],                           \
                             ah[0], ah[1], ah[2], ah[3], bl[ng][s], bl[ng][s + 2]); \
                    if (!two_term)                                             \
                        MMA16816(d[0], d[1], d[2], d[3],                       \
                                 al[0], al[1], al[2], al[3], bh[ng][s], bh[ng][s + 2]); \
                }                                                              \
            }                                                                  \
        }                                                                      \
        __syncthreads();                                                       \
    }

#define LOAD_STAGE(buf, kb) do {                                               \
        const int _k0 = (kb) * KC;                                             \
        const uint32_t _sb = sbase + (buf) * STAGE_B;                          \
        CP16(_sb + so0,              pAh + gA + _k0);                          \
        CP16(_sb + so1,              pAh + gA + _k0 + 8);                      \
        CP16(_sb + TILE_B + so0,     pAl + gA + _k0);                          \
        CP16(_sb + TILE_B + so1,     pAl + gA + _k0 + 8);                      \
        CP16(_sb + 2*TILE_B + so0,   pBh + gB + _k0);                          \
        CP16(_sb + 2*TILE_B + so1,   pBh + gB + _k0 + 8);                      \
        CP16(_sb + 3*TILE_B + so0,   pBl + gB + _k0);                          \
        CP16(_sb + 3*TILE_B + so1,   pBl + gB + _k0 + 8);                      \
        CP_COMMIT();                                                           \
    } while (0)

// ---------------------------------------------------------------------------
// Fused QKV projection: grid (DIM/BN, M/BM, 3); bz selects Wq/Wk/Wv.
// bz 0/1 -> row-major hi/lo (Q/K); bz 2 -> transposed hi/lo (V).
// Always 3-term (feeds everything downstream).
// ---------------------------------------------------------------------------
__global__ void __launch_bounds__(THREADS, 1)
qkv_gemm(const __half* __restrict__ Ah, const __half* __restrict__ Al,
         const __half* __restrict__ W0h, const __half* __restrict__ W0l,
         const __half* __restrict__ W1h, const __half* __restrict__ W1l,
         const __half* __restrict__ W2h, const __half* __restrict__ W2l,
         const float* __restrict__ b0, const float* __restrict__ b1,
         const float* __restrict__ b2,
         __half* __restrict__ Q0h, __half* __restrict__ Q0l,
         __half* __restrict__ Q1h, __half* __restrict__ Q1l)
{
    const int bx = blockIdx.x, by = blockIdx.y, wsel = blockIdx.z;
    const int two_term = 0;

    extern __shared__ __align__(1024) char smem[];
    const uint32_t sbase = smem_u32(smem);

    const int tid  = threadIdx.x;
    const int lane = tid & 31;
    const int wid  = tid >> 5;
    const int wm   = wid & 3;
    const int wn   = wid >> 2;

    const int ldA = DIM, ldB = DIM;
    const int nkb = DIM / KC;

    const __half* pBh = wsel == 0 ? W0h : (wsel == 1 ? W1h : W2h);
    const __half* pBl = wsel == 0 ? W0l : (wsel == 1 ? W1l : W2l);
    const float*  bias = wsel == 0 ? b0 : (wsel == 1 ? b1 : b2);

    const __half* pAh = Ah + (size_t)by * BM * ldA;
    const __half* pAl = Al + (size_t)by * BM * ldA;
    pBh += (size_t)bx * BN * ldB;
    pBl += (size_t)bx * BN * ldB;

    const int lrow = tid >> 2;
    const int lc   = (tid & 3) * 2;
    const uint32_t so0 = sw128(lrow * 128 + lc * 16);
    const uint32_t so1 = sw128(lrow * 128 + lc * 16 + 16);
    const size_t gA = (size_t)lrow * ldA + lc * 8;
    const size_t gB = (size_t)lrow * ldB + lc * 8;

    float acc[2][4][4];
#pragma unroll
    for (int i = 0; i < 2; i++)
#pragma unroll
        for (int j = 0; j < 4; j++)
#pragma unroll
            for (int c = 0; c < 4; c++) acc[i][j][c] = 0.0f;

    const int lr  = lane & 7;
    const int grp = lane >> 3;
    const int lm_row_off = lr + ((grp & 1) << 3);
    const int lm_col_off = (grp >> 1) << 4;

    GEMM_MAINLOOP();

    const int r0 = by * BM + wm * 32 + (lane >> 2);
    const int c0 = bx * BN + wn * 32 + ((lane & 3) << 1);

    if (wsel < 2) {
        __half* Ch = wsel == 0 ? Q0h : Q1h;
        __half* Cl = wsel == 0 ? Q0l : Q1l;
#pragma unroll
        for (int mt = 0; mt < 2; mt++) {
#pragma unroll
            for (int nt = 0; nt < 4; nt++) {
                int row = r0 + mt * 16;
                int col = c0 + nt * 8;
                float b0f = bias[col], b1f = bias[col + 1];
                float v0 = acc[mt][nt][0] + b0f;
                float v1 = acc[mt][nt][1] + b1f;
                float v2 = acc[mt][nt][2] + b0f;
                float v3 = acc[mt][nt][3] + b1f;
                __half h0, h1, h2, h3, l0, l1, l2, l3;
                split1(v0, h0, l0); split1(v1, h1, l1);
                split1(v2, h2, l2); split1(v3, h3, l3);
                size_t o0 = (size_t)row * DIM + col;
                size_t o1 = o0 + 8ull * DIM;
                *(__half2*)(Ch + o0) = __halves2half2(h0, h1);
                *(__half2*)(Cl + o0) = __halves2half2(l0, l1);
                *(__half2*)(Ch + o1) = __halves2half2(h2, h3);
                *(__half2*)(Cl + o1) = __halves2half2(l2, l3);
            }
        }
    } else {
        // V -> transposed [b][d][s]
#pragma unroll
        for (int mt = 0; mt < 2; mt++) {
            int row = r0 + mt * 16;
            int b = row >> 11;
            int s = row & (SEQ - 1);
            __half* dh = g_vth + (size_t)b * DIM * SEQ + s;
            __half* dl = g_vtl + (size_t)b * DIM * SEQ + s;
#pragma unroll
            for (int nt = 0; nt < 4; nt++) {
                int col = c0 + nt * 8;
                float b0f = bias[col], b1f = bias[col + 1];
                __half h, l;
                split1(acc[mt][nt][0] + b0f, h, l);
                dh[(size_t)col * SEQ] = h;       dl[(size_t)col * SEQ] = l;
                split1(acc[mt][nt][1] + b1f, h, l);
                dh[(size_t)(col + 1) * SEQ] = h; dl[(size_t)(col + 1) * SEQ] = l;
                split1(acc[mt][nt][2] + b0f, h, l);
                dh[(size_t)col * SEQ + 8] = h;   dl[(size_t)col * SEQ + 8] = l;
                split1(acc[mt][nt][3] + b1f, h, l);
                dh[(size_t)(col + 1) * SEQ + 8] = h; dl[(size_t)(col + 1) * SEQ + 8] = l;
            }
        }
    }
}

// ---------------------------------------------------------------------------
// Generic NT GEMM (scores / PV), fp32 output only.
// ---------------------------------------------------------------------------
__global__ void __launch_bounds__(THREADS, 1)
tc_gemm(const __half* __restrict__ Ah_, const __half* __restrict__ Al_,
        const __half* __restrict__ Bh_, const __half* __restrict__ Bl_,
        float* __restrict__ C,
        int K, int ldA, int ldB, int ldC, float scale, int flags,
        long long sA, long long sB, long long sC)
{
    const int bx = blockIdx.x, bz = blockIdx.z;
    int by = blockIdx.y;
    if (flags & F_REV_Y) by = gridDim.y - 1 - by;
    if ((flags & F_CAUSAL_SKIP) && bx > by) return;
    const int two_term = flags & F_TWO_TERM;

    extern __shared__ __align__(1024) char smem[];
    const uint32_t sbase = smem_u32(smem);

    const int tid  = threadIdx.x;
    const int lane = tid & 31;
    const int wid  = tid >> 5;
    const int wm   = wid & 3;
    const int wn   = wid >> 2;

    int kend = K;
    if (flags & F_CAUSAL_KLIM) kend = min(K, (by + 1) * BM);
    const int nkb = kend / KC;

    const size_t aoff = (size_t)bz * sA + (size_t)by * BM * ldA;
    const size_t boff = (size_t)bz * sB + (size_t)bx * BN * ldB;
    const __half* pAh = Ah_ + aoff;
    const __half* pAl = Al_ + aoff;
    const __half* pBh = Bh_ + boff;
    const __half* pBl = Bl_ + boff;

    const int lrow = tid >> 2;
    const int lc   = (tid & 3) * 2;
    const uint32_t so0 = sw128(lrow * 128 + lc * 16);
    const uint32_t so1 = sw128(lrow * 128 + lc * 16 + 16);
    const size_t gA = (size_t)lrow * ldA + lc * 8;
    const size_t gB = (size_t)lrow * ldB + lc * 8;

    float acc[2][4][4];
#pragma unroll
    for (int i = 0; i < 2; i++)
#pragma unroll
        for (int j = 0; j < 4; j++)
#pragma unroll
            for (int c = 0; c < 4; c++) acc[i][j][c] = 0.0f;

    const int lr  = lane & 7;
    const int grp = lane >> 3;
    const int lm_row_off = lr + ((grp & 1) << 3);
    const int lm_col_off = (grp >> 1) << 4;

    GEMM_MAINLOOP();

    const int r0 = by * BM + wm * 32 + (lane >> 2);
    const int c0 = bx * BN + wn * 32 + ((lane & 3) << 1);

#pragma unroll
    for (int mt = 0; mt < 2; mt++) {
#pragma unroll
        for (int nt = 0; nt < 4; nt++) {
            int row = r0 + mt * 16;
            int col = c0 + nt * 8;
            float* dst = C + (size_t)bz * sC + (size_t)row * ldC + col;
            *(float2*)dst = make_float2(acc[mt][nt][0] * scale,
                                        acc[mt][nt][1] * scale);
            *(float2*)(dst + 8ull * ldC) = make_float2(acc[mt][nt][2] * scale,
                                                       acc[mt][nt][3] * scale);
        }
    }
}

// ---------------------------------------------------------------------------
// elementwise fp32 -> (hi, lo) fp16 split, float4-vectorized
// ---------------------------------------------------------------------------
__global__ void __launch_bounds__(256)
split_f32(const float* __restrict__ x, __half* __restrict__ h,
          __half* __restrict__ l, int n4)
{
    int i = blockIdx.x * blockDim.x + threadIdx.x;
    if (i >= n4) return;
    float4 v = ((const float4*)x)[i];
    __half hx = __float2half_rn(v.x), hy = __float2half_rn(v.y);
    __half hz = __float2half_rn(v.z), hw = __float2half_rn(v.w);
    __half2 H0 = __halves2half2(hx, hy), H1 = __halves2half2(hz, hw);
    __half2 L0 = __floats2half2_rn(v.x - __half2float(hx), v.y - __half2float(hy));
    __half2 L1 = __floats2half2_rn(v.z - __half2float(hz), v.w - __half2float(hw));
    ((__half2*)h)[i * 2]     = H0;
    ((__half2*)h)[i * 2 + 1] = H1;
    ((__half2*)l)[i * 2]     = L0;
    ((__half2*)l)[i * 2 + 1] = L1;
}

// ---------------------------------------------------------------------------
// Causal row softmax: fp32 scores -> hi/lo fp16 probabilities (zero tails)
// ---------------------------------------------------------------------------
__global__ void __launch_bounds__(256)
causal_softmax(const float* __restrict__ S, __half* __restrict__ Ph,
               __half* __restrict__ Pl, int seq)
{
    int r = blockIdx.x;
    int b = blockIdx.y;
    size_t base = ((size_t)b * seq + (size_t)r) * seq;
    const float* row = S + base;
    int n = r + 1;
    int tid = threadIdx.x;

    __shared__ float red[256];

    float m = -1e30f;
    for (int j = tid; j < n; j += 256) m = fmaxf(m, row[j]);
    red[tid] = m; __syncthreads();
    for (int s = 128; s > 0; s >>= 1) {
        if (tid < s) red[tid] = fmaxf(red[tid], red[tid + s]);
        __syncthreads();
    }
    m = red[0]; __syncthreads();

    float ev[8];
    int cnt = 0;
    float sum = 0.0f;
    for (int j = tid; j < n; j += 256) {
        float e = __expf(row[j] - m);
        ev[cnt++] = e;
        sum += e;
    }
    red[tid] = sum; __syncthreads();
    for (int s = 128; s > 0; s >>= 1) {
        if (tid < s) red[tid] += red[tid + s];
        __syncthreads();
    }
    float inv = 1.0f / red[0];

    cnt = 0;
    for (int j = tid; j < n; j += 256) {
        float p = ev[cnt++] * inv;
        __half h = __float2half_rn(p);
        Ph[base + j] = h;
        Pl[base + j] = __float2half_rn(p - __half2float(h));
    }
    __half z = __float2half_rn(0.0f);
    for (int j = n + tid; j < seq; j += 256) {
        Ph[base + j] = z;
        Pl[base + j] = z;
    }
}

// ---------------------------------------------------------------------------
extern "C" void kernel_launch(void* const* d_in, const int* in_sizes, int n_in,
                              void* d_out, int out_size)
{
    const float* X  = (const float*)d_in[0];
    const float* Wq = (const float*)d_in[1];
    const float* bq = (const float*)d_in[2];
    const float* Wk = (const float*)d_in[3];
    const float* bk = (const float*)d_in[4];
    const float* Wv = (const float*)d_in[5];
    const float* bv = (const float*)d_in[6];
    float* out = (float*)d_out;

    __half *xh, *xl, *wqh, *wql, *wkh, *wkl, *wvh, *wvl;
    __half *qh, *ql, *kh, *kl, *vth, *vtl, *ph, *pl;
    float* sp;
    cudaGetSymbolAddress((void**)&xh,  g_xh);  cudaGetSymbolAddress((void**)&xl,  g_xl);
    cudaGetSymbolAddress((void**)&wqh, g_wqh); cudaGetSymbolAddress((void**)&wql, g_wql);
    cudaGetSymbolAddress((void**)&wkh, g_wkh); cudaGetSymbolAddress((void**)&wkl, g_wkl);
    cudaGetSymbolAddress((void**)&wvh, g_wvh); cudaGetSymbolAddress((void**)&wvl, g_wvl);
    cudaGetSymbolAddress((void**)&qh,  g_qh);  cudaGetSymbolAddress((void**)&ql,  g_ql);
    cudaGetSymbolAddress((void**)&kh,  g_kh);  cudaGetSymbolAddress((void**)&kl,  g_kl);
    cudaGetSymbolAddress((void**)&vth, g_vth); cudaGetSymbolAddress((void**)&vtl, g_vtl);
    cudaGetSymbolAddress((void**)&ph,  g_ph);  cudaGetSymbolAddress((void**)&pl,  g_pl);
    cudaGetSymbolAddress((void**)&sp,  g_s);

    static int smem_set = 0;
    if (!smem_set) {
        cudaFuncSetAttribute(tc_gemm,  cudaFuncAttributeMaxDynamicSharedMemorySize, SMEM_TOTAL);
        cudaFuncSetAttribute(qkv_gemm, cudaFuncAttributeMaxDynamicSharedMemorySize, SMEM_TOTAL);
        smem_set = 1;
    }

    const int M = BATCH * SEQ;                       // 8192
    const long long sQK = (long long)SEQ * DIM;
    const long long sVT = (long long)DIM * SEQ;
    const long long sSS = (long long)SEQ * SEQ;

    // 0) pre-split inputs into hi/lo fp16
    split_f32<<<(NX / 4 + 255) / 256, 256>>>(X,  xh,  xl,  NX / 4);
    split_f32<<<(NW / 4 + 255) / 256, 256>>>(Wq, wqh, wql, NW / 4);
    split_f32<<<(NW / 4 + 255) / 256, 256>>>(Wk, wkh, wkl, NW / 4);
    split_f32<<<(NW / 4 + 255) / 256, 256>>>(Wv, wvh, wvl, NW / 4);

    // 1) fused QKV projections (one launch, bz selects weight/output)
    {
        dim3 grid(DIM / BN, M / BM, 3);
        qkv_gemm<<<grid, THREADS, SMEM_TOTAL>>>(xh, xl,
                                                wqh, wql, wkh, wkl, wvh, wvl,
                                                bq, bk, bv,
                                                qh, ql, kh, kl);
    }

    // 2) scores = (Q @ K^T) / 32, fp32, causal tiles only, 2-term, heavy-first
    {
        dim3 grid(SEQ / BN, SEQ / BM, BATCH);
        tc_gemm<<<grid, THREADS, SMEM_TOTAL>>>(qh, ql, kh, kl, sp,
                                               DIM, DIM, DIM, SEQ, 0.03125f,
                                               F_CAUSAL_SKIP | F_TWO_TERM | F_REV_Y,
                                               sQK, sQK, sSS);
    }

    // 3) causal softmax -> hi/lo fp16 P
    {
        dim3 grid(SEQ, BATCH);
        causal_softmax<<<grid, 256>>>(sp, ph, pl, SEQ);
    }

    // 4) out = P @ Vt^T  (fp32 out; causal K-limit, 2-term, heavy-first)
    {
        dim3 grid(DIM / BN, SEQ / BM, BATCH);
        tc_gemm<<<grid, THREADS, SMEM_TOTAL>>>(ph, pl, vth, vtl, out,
                                               SEQ, SEQ, SEQ, DIM, 1.0f,
                                               F_CAUSAL_KLIM | F_TWO_TERM | F_REV_Y,
                                               sSS, sVT, sQK);
    }
}

// round 15
// speedup vs baseline: 1.7048x; 1.3848x over previous
#include <cuda_runtime.h>
#include <cuda_fp16.h>
#include <cstdint>
#include <math.h>

// Problem constants
#define BATCH 4
#define SEQ   2048
#define DIM   1024

#define BM 128
#define BN 128
#define KC 64            // K elements (halfs) per stage (128B rows, SW128)
#define THREADS 512
#define NSTAGE 2

// flags
#define F_CAUSAL_SKIP  1
#define F_CAUSAL_KLIM  2
#define F_REV_Y        32

#define NX (BATCH * SEQ * DIM)   // 8M
#define NW (DIM * DIM)           // 1M
#define NS (BATCH * SEQ * SEQ)   // 16M

// smem: 3 tiles (Ah,Bh,Bl) x 16KB = 48KB per stage, 2 stages = 96KB
#define TILE_B  (BM * KC * 2)    // 16384
#define OFF_BH  TILE_B
#define OFF_BL  (2 * TILE_B)
#define STAGE_B (3 * TILE_B)     // 49152
#define SMEM_TOTAL (NSTAGE * STAGE_B)   // 98304

// Scratch (allocation-free)
__device__ __half g_xh[NX];
__device__ __half g_wqh[NW], g_wql[NW];
__device__ __half g_wkh[NW], g_wkl[NW];
__device__ __half g_wvh[NW], g_wvl[NW];
__device__ __half g_qh[NX];               // Q hi only (scores A-operand)
__device__ __half g_kh[NX],  g_kl[NX];
__device__ __half g_vth[NX], g_vtl[NX];   // V transposed [b][d][s]
__device__ float  g_s[NS];
__device__ __half g_ph[NS];               // P hi only (PV A-operand)

__device__ __forceinline__ uint32_t smem_u32(const void* p) {
    uint32_t a;
    asm("{ .reg .u64 t; cvta.to.shared.u64 t, %1; cvt.u32.u64 %0, t; }" : "=r"(a) : "l"(p));
    return a;
}

#define LDMATRIX_X4(r0, r1, r2, r3, addr)                                      \
    asm volatile("ldmatrix.sync.aligned.m8n8.x4.shared.b16 {%0,%1,%2,%3}, [%4];" \
        : "=r"(r0), "=r"(r1), "=r"(r2), "=r"(r3) : "r"(addr))

#define MMA16816(d0, d1, d2, d3, a0, a1, a2, a3, b0, b1)                       \
    asm volatile("mma.sync.aligned.m16n8k16.row.col.f32.f16.f16.f32 "          \
        "{%0,%1,%2,%3},{%4,%5,%6,%7},{%8,%9},{%0,%1,%2,%3};"                   \
        : "+f"(d0), "+f"(d1), "+f"(d2), "+f"(d3)                               \
        : "r"(a0), "r"(a1), "r"(a2), "r"(a3), "r"(b0), "r"(b1))

#define CP16(dst, src) \
    asm volatile("cp.async.cg.shared.global [%0], [%1], 16;" :: "r"(dst), "l"(src))
#define CP_COMMIT()  asm volatile("cp.async.commit_group;" ::: "memory")
#define CP_WAIT1()   asm volatile("cp.async.wait_group 1;" ::: "memory")
#define CP_WAIT0()   asm volatile("cp.async.wait_group 0;" ::: "memory")

// SW128 swizzle for 128-byte rows (KC=64 halfs)
__device__ __forceinline__ uint32_t sw128(uint32_t off) {
    return off ^ ((off >> 3) & 0x70);
}

// split fp32 -> fp16 hi + fp16 residual
__device__ __forceinline__ void split1(float x, __half& h, __half& l) {
    h = __float2half_rn(x);
    l = __float2half_rn(x - __half2float(h));
}

// ---------------------------------------------------------------------------
// 2-term mainloop: acc += Ah*(Bh+Bl). A hi-only (calibrated err ~1.4e-4/GEMM).
// Requires in scope: sbase, pAh,pBh,pBl, gA,gB, so0,so1, nkb, acc,
// lm_row_off, lm_col_off, wm, wn.
// ---------------------------------------------------------------------------
#define LOAD_STAGE(buf, kb) do {                                               \
        const int _k0 = (kb) * KC;                                             \
        const uint32_t _sb = sbase + (buf) * STAGE_B;                          \
        CP16(_sb + so0,           pAh + gA + _k0);                             \
        CP16(_sb + so1,           pAh + gA + _k0 + 8);                         \
        CP16(_sb + OFF_BH + so0,  pBh + gB + _k0);                             \
        CP16(_sb + OFF_BH + so1,  pBh + gB + _k0 + 8);                         \
        CP16(_sb + OFF_BL + so0,  pBl + gB + _k0);                             \
        CP16(_sb + OFF_BL + so1,  pBl + gB + _k0 + 8);                         \
        CP_COMMIT();                                                           \
    } while (0)

#define GEMM_MAINLOOP()                                                        \
    LOAD_STAGE(0, 0);                                                          \
    for (int kb = 0; kb < nkb; kb++) {                                         \
        const int buf = kb & 1;                                                \
        if (kb + 1 < nkb) { LOAD_STAGE(buf ^ 1, kb + 1); CP_WAIT1(); }         \
        else             { CP_WAIT0(); }                                       \
        __syncthreads();                                                       \
        const uint32_t uAh = sbase + buf * STAGE_B;                            \
        const uint32_t uBh = uAh + OFF_BH;                                     \
        const uint32_t uBl = uAh + OFF_BL;                                     \
        _Pragma("unroll")                                                      \
        for (int ks = 0; ks < 4; ks++) {                                       \
            const uint32_t kbyte = ks * 32 + lm_col_off;                       \
            uint32_t bh[2][4], bl[2][4];                                       \
            _Pragma("unroll")                                                  \
            for (int ng = 0; ng < 2; ng++) {                                   \
                int nrow = wn * 32 + ng * 16 + lm_row_off;                     \
                uint32_t off = sw128(nrow * 128 + kbyte);                      \
                LDMATRIX_X4(bh[ng][0], bh[ng][1], bh[ng][2], bh[ng][3], uBh + off); \
                LDMATRIX_X4(bl[ng][0], bl[ng][1], bl[ng][2], bl[ng][3], uBl + off); \
            }                                                                  \
            _Pragma("unroll")                                                  \
            for (int mt = 0; mt < 2; mt++) {                                   \
                int mrow = wm * 32 + mt * 16 + lm_row_off;                     \
                uint32_t off = sw128(mrow * 128 + kbyte);                      \
                uint32_t ah[4];                                                \
                LDMATRIX_X4(ah[0], ah[1], ah[2], ah[3], uAh + off);            \
                _Pragma("unroll")                                              \
                for (int nt = 0; nt < 4; nt++) {                               \
                    const int ng = nt >> 1, s = nt & 1;                        \
                    float* d = acc[mt][nt];                                    \
                    MMA16816(d[0], d[1], d[2], d[3],                           \
                             ah[0], ah[1], ah[2], ah[3], bh[ng][s], bh[ng][s + 2]); \
                    MMA16816(d[0], d[1], d[2], d[3],                           \
                             ah[0], ah[1], ah[2], ah[3], bl[ng][s], bl[ng][s + 2]); \
                }                                                              \
            }                                                                  \
        }                                                                      \
        __syncthreads();                                                       \
    }

// ---------------------------------------------------------------------------
// Fused QKV projection: grid (DIM/BN, M/BM, 3); bz selects Wq/Wk/Wv.
// wsel 0 -> Q hi only; wsel 1 -> K hi/lo; wsel 2 -> V transposed hi/lo.
// ---------------------------------------------------------------------------
__global__ void __launch_bounds__(THREADS, 1)
qkv_gemm(const __half* __restrict__ Xh,
         const __half* __restrict__ W0h, const __half* __restrict__ W0l,
         const __half* __restrict__ W1h, const __half* __restrict__ W1l,
         const __half* __restrict__ W2h, const __half* __restrict__ W2l,
         const float* __restrict__ b0, const float* __restrict__ b1,
         const float* __restrict__ b2,
         __half* __restrict__ Qh,
         __half* __restrict__ Kh, __half* __restrict__ Kl)
{
    const int bx = blockIdx.x, by = blockIdx.y, wsel = blockIdx.z;

    extern __shared__ __align__(1024) char smem[];
    const uint32_t sbase = smem_u32(smem);

    const int tid  = threadIdx.x;
    const int lane = tid & 31;
    const int wid  = tid >> 5;
    const int wm   = wid & 3;
    const int wn   = wid >> 2;

    const int ldA = DIM, ldB = DIM;
    const int nkb = DIM / KC;

    const __half* pBh = wsel == 0 ? W0h : (wsel == 1 ? W1h : W2h);
    const __half* pBl = wsel == 0 ? W0l : (wsel == 1 ? W1l : W2l);
    const float*  bias = wsel == 0 ? b0 : (wsel == 1 ? b1 : b2);

    const __half* pAh = Xh + (size_t)by * BM * ldA;
    pBh += (size_t)bx * BN * ldB;
    pBl += (size_t)bx * BN * ldB;

    const int lrow = tid >> 2;
    const int lc   = (tid & 3) * 2;
    const uint32_t so0 = sw128(lrow * 128 + lc * 16);
    const uint32_t so1 = sw128(lrow * 128 + lc * 16 + 16);
    const size_t gA = (size_t)lrow * ldA + lc * 8;
    const size_t gB = (size_t)lrow * ldB + lc * 8;

    float acc[2][4][4];
#pragma unroll
    for (int i = 0; i < 2; i++)
#pragma unroll
        for (int j = 0; j < 4; j++)
#pragma unroll
            for (int c = 0; c < 4; c++) acc[i][j][c] = 0.0f;

    const int lr  = lane & 7;
    const int grp = lane >> 3;
    const int lm_row_off = lr + ((grp & 1) << 3);
    const int lm_col_off = (grp >> 1) << 4;

    GEMM_MAINLOOP();

    const int r0 = by * BM + wm * 32 + (lane >> 2);
    const int c0 = bx * BN + wn * 32 + ((lane & 3) << 1);

    if (wsel == 0) {
        // Q: hi only
#pragma unroll
        for (int mt = 0; mt < 2; mt++) {
#pragma unroll
            for (int nt = 0; nt < 4; nt++) {
                int row = r0 + mt * 16;
                int col = c0 + nt * 8;
                float b0f = bias[col], b1f = bias[col + 1];
                size_t o0 = (size_t)row * DIM + col;
                size_t o1 = o0 + 8ull * DIM;
                *(__half2*)(Qh + o0) = __floats2half2_rn(acc[mt][nt][0] + b0f,
                                                         acc[mt][nt][1] + b1f);
                *(__half2*)(Qh + o1) = __floats2half2_rn(acc[mt][nt][2] + b0f,
                                                         acc[mt][nt][3] + b1f);
            }
        }
    } else if (wsel == 1) {
        // K: hi + lo
#pragma unroll
        for (int mt = 0; mt < 2; mt++) {
#pragma unroll
            for (int nt = 0; nt < 4; nt++) {
                int row = r0 + mt * 16;
                int col = c0 + nt * 8;
                float b0f = bias[col], b1f = bias[col + 1];
                float v0 = acc[mt][nt][0] + b0f;
                float v1 = acc[mt][nt][1] + b1f;
                float v2 = acc[mt][nt][2] + b0f;
                float v3 = acc[mt][nt][3] + b1f;
                __half h0, h1, h2, h3, l0, l1, l2, l3;
                split1(v0, h0, l0); split1(v1, h1, l1);
                split1(v2, h2, l2); split1(v3, h3, l3);
                size_t o0 = (size_t)row * DIM + col;
                size_t o1 = o0 + 8ull * DIM;
                *(__half2*)(Kh + o0) = __halves2half2(h0, h1);
                *(__half2*)(Kl + o0) = __halves2half2(l0, l1);
                *(__half2*)(Kh + o1) = __halves2half2(h2, h3);
                *(__half2*)(Kl + o1) = __halves2half2(l2, l3);
            }
        }
    } else {
        // V -> transposed [b][d][s], hi + lo
#pragma unroll
        for (int mt = 0; mt < 2; mt++) {
            int row = r0 + mt * 16;
            int b = row >> 11;
            int s = row & (SEQ - 1);
            __half* dh = g_vth + (size_t)b * DIM * SEQ + s;
            __half* dl = g_vtl + (size_t)b * DIM * SEQ + s;
#pragma unroll
            for (int nt = 0; nt < 4; nt++) {
                int col = c0 + nt * 8;
                float b0f = bias[col], b1f = bias[col + 1];
                __half h, l;
                split1(acc[mt][nt][0] + b0f, h, l);
                dh[(size_t)col * SEQ] = h;       dl[(size_t)col * SEQ] = l;
                split1(acc[mt][nt][1] + b1f, h, l);
                dh[(size_t)(col + 1) * SEQ] = h; dl[(size_t)(col + 1) * SEQ] = l;
                split1(acc[mt][nt][2] + b0f, h, l);
                dh[(size_t)col * SEQ + 8] = h;   dl[(size_t)col * SEQ + 8] = l;
                split1(acc[mt][nt][3] + b1f, h, l);
                dh[(size_t)(col + 1) * SEQ + 8] = h; dl[(size_t)(col + 1) * SEQ + 8] = l;
            }
        }
    }
}

// ---------------------------------------------------------------------------
// Generic 2-term NT GEMM (scores / PV): A hi-only, B hi/lo, fp32 out.
// ---------------------------------------------------------------------------
__global__ void __launch_bounds__(THREADS, 1)
tc_gemm(const __half* __restrict__ Ah_,
        const __half* __restrict__ Bh_, const __half* __restrict__ Bl_,
        float* __restrict__ C,
        int K, int ldA, int ldB, int ldC, float scale, int flags,
        long long sA, long long sB, long long sC)
{
    const int bx = blockIdx.x, bz = blockIdx.z;
    int by = blockIdx.y;
    if (flags & F_REV_Y) by = gridDim.y - 1 - by;
    if ((flags & F_CAUSAL_SKIP) && bx > by) return;

    extern __shared__ __align__(1024) char smem[];
    const uint32_t sbase = smem_u32(smem);

    const int tid  = threadIdx.x;
    const int lane = tid & 31;
    const int wid  = tid >> 5;
    const int wm   = wid & 3;
    const int wn   = wid >> 2;

    int kend = K;
    if (flags & F_CAUSAL_KLIM) kend = min(K, (by + 1) * BM);
    const int nkb = kend / KC;

    const size_t aoff = (size_t)bz * sA + (size_t)by * BM * ldA;
    const size_t boff = (size_t)bz * sB + (size_t)bx * BN * ldB;
    const __half* pAh = Ah_ + aoff;
    const __half* pBh = Bh_ + boff;
    const __half* pBl = Bl_ + boff;

    const int lrow = tid >> 2;
    const int lc   = (tid & 3) * 2;
    const uint32_t so0 = sw128(lrow * 128 + lc * 16);
    const uint32_t so1 = sw128(lrow * 128 + lc * 16 + 16);
    const size_t gA = (size_t)lrow * ldA + lc * 8;
    const size_t gB = (size_t)lrow * ldB + lc * 8;

    float acc[2][4][4];
#pragma unroll
    for (int i = 0; i < 2; i++)
#pragma unroll
        for (int j = 0; j < 4; j++)
#pragma unroll
            for (int c = 0; c < 4; c++) acc[i][j][c] = 0.0f;

    const int lr  = lane & 7;
    const int grp = lane >> 3;
    const int lm_row_off = lr + ((grp & 1) << 3);
    const int lm_col_off = (grp >> 1) << 4;

    GEMM_MAINLOOP();

    const int r0 = by * BM + wm * 32 + (lane >> 2);
    const int c0 = bx * BN + wn * 32 + ((lane & 3) << 1);

#pragma unroll
    for (int mt = 0; mt < 2; mt++) {
#pragma unroll
        for (int nt = 0; nt < 4; nt++) {
            int row = r0 + mt * 16;
            int col = c0 + nt * 8;
            float* dst = C + (size_t)bz * sC + (size_t)row * ldC + col;
            *(float2*)dst = make_float2(acc[mt][nt][0] * scale,
                                        acc[mt][nt][1] * scale);
            *(float2*)(dst + 8ull * ldC) = make_float2(acc[mt][nt][2] * scale,
                                                       acc[mt][nt][3] * scale);
        }
    }
}

// ---------------------------------------------------------------------------
// fp32 -> hi-only fp16
// ---------------------------------------------------------------------------
__global__ void __launch_bounds__(256)
split_hi(const float* __restrict__ x, __half* __restrict__ h, int n4)
{
    int i = blockIdx.x * blockDim.x + threadIdx.x;
    if (i >= n4) return;
    float4 v = ((const float4*)x)[i];
    ((__half2*)h)[i * 2]     = __floats2half2_rn(v.x, v.y);
    ((__half2*)h)[i * 2 + 1] = __floats2half2_rn(v.z, v.w);
}

// fp32 -> (hi, lo) fp16 split
__global__ void __launch_bounds__(256)
split_f32(const float* __restrict__ x, __half* __restrict__ h,
          __half* __restrict__ l, int n4)
{
    int i = blockIdx.x * blockDim.x + threadIdx.x;
    if (i >= n4) return;
    float4 v = ((const float4*)x)[i];
    __half hx = __float2half_rn(v.x), hy = __float2half_rn(v.y);
    __half hz = __float2half_rn(v.z), hw = __float2half_rn(v.w);
    ((__half2*)h)[i * 2]     = __halves2half2(hx, hy);
    ((__half2*)h)[i * 2 + 1] = __halves2half2(hz, hw);
    ((__half2*)l)[i * 2]     = __floats2half2_rn(v.x - __half2float(hx), v.y - __half2float(hy));
    ((__half2*)l)[i * 2 + 1] = __floats2half2_rn(v.z - __half2float(hz), v.w - __half2float(hw));
}

// ---------------------------------------------------------------------------
// Causal row softmax: fp32 scores -> hi-only fp16 probabilities (zero tails)
// ---------------------------------------------------------------------------
__global__ void __launch_bounds__(256)
causal_softmax(const float* __restrict__ S, __half* __restrict__ Ph, int seq)
{
    int r = blockIdx.x;
    int b = blockIdx.y;
    size_t base = ((size_t)b * seq + (size_t)r) * seq;
    const float* row = S + base;
    int n = r + 1;
    int tid = threadIdx.x;

    __shared__ float red[256];

    float m = -1e30f;
    for (int j = tid; j < n; j += 256) m = fmaxf(m, row[j]);
    red[tid] = m; __syncthreads();
    for (int s = 128; s > 0; s >>= 1) {
        if (tid < s) red[tid] = fmaxf(red[tid], red[tid + s]);
        __syncthreads();
    }
    m = red[0]; __syncthreads();

    float ev[8];
    int cnt = 0;
    float sum = 0.0f;
    for (int j = tid; j < n; j += 256) {
        float e = __expf(row[j] - m);
        ev[cnt++] = e;
        sum += e;
    }
    red[tid] = sum; __syncthreads();
    for (int s = 128; s > 0; s >>= 1) {
        if (tid < s) red[tid] += red[tid + s];
        __syncthreads();
    }
    float inv = 1.0f / red[0];

    cnt = 0;
    for (int j = tid; j < n; j += 256)
        Ph[base + j] = __float2half_rn(ev[cnt++] * inv);
    __half z = __float2half_rn(0.0f);
    for (int j = n + tid; j < seq; j += 256)
        Ph[base + j] = z;
}

// ---------------------------------------------------------------------------
extern "C" void kernel_launch(void* const* d_in, const int* in_sizes, int n_in,
                              void* d_out, int out_size)
{
    const float* X  = (const float*)d_in[0];
    const float* Wq = (const float*)d_in[1];
    const float* bq = (const float*)d_in[2];
    const float* Wk = (const float*)d_in[3];
    const float* bk = (const float*)d_in[4];
    const float* Wv = (const float*)d_in[5];
    const float* bv = (const float*)d_in[6];
    float* out = (float*)d_out;

    __half *xh, *wqh, *wql, *wkh, *wkl, *wvh, *wvl;
    __half *qh, *kh, *kl, *vth, *vtl, *ph;
    float* sp;
    cudaGetSymbolAddress((void**)&xh,  g_xh);
    cudaGetSymbolAddress((void**)&wqh, g_wqh); cudaGetSymbolAddress((void**)&wql, g_wql);
    cudaGetSymbolAddress((void**)&wkh, g_wkh); cudaGetSymbolAddress((void**)&wkl, g_wkl);
    cudaGetSymbolAddress((void**)&wvh, g_wvh); cudaGetSymbolAddress((void**)&wvl, g_wvl);
    cudaGetSymbolAddress((void**)&qh,  g_qh);
    cudaGetSymbolAddress((void**)&kh,  g_kh);  cudaGetSymbolAddress((void**)&kl,  g_kl);
    cudaGetSymbolAddress((void**)&vth, g_vth); cudaGetSymbolAddress((void**)&vtl, g_vtl);
    cudaGetSymbolAddress((void**)&ph,  g_ph);
    cudaGetSymbolAddress((void**)&sp,  g_s);

    static int smem_set = 0;
    if (!smem_set) {
        cudaFuncSetAttribute(tc_gemm,  cudaFuncAttributeMaxDynamicSharedMemorySize, SMEM_TOTAL);
        cudaFuncSetAttribute(qkv_gemm, cudaFuncAttributeMaxDynamicSharedMemorySize, SMEM_TOTAL);
        smem_set = 1;
    }

    const int M = BATCH * SEQ;                       // 8192
    const long long sQK = (long long)SEQ * DIM;
    const long long sVT = (long long)DIM * SEQ;
    const long long sSS = (long long)SEQ * SEQ;

    // 0) pre-split: X hi-only; weights hi/lo
    split_hi <<<(NX / 4 + 255) / 256, 256>>>(X,  xh,  NX / 4);
    split_f32<<<(NW / 4 + 255) / 256, 256>>>(Wq, wqh, wql, NW / 4);
    split_f32<<<(NW / 4 + 255) / 256, 256>>>(Wk, wkh, wkl, NW / 4);
    split_f32<<<(NW / 4 + 255) / 256, 256>>>(Wv, wvh, wvl, NW / 4);

    // 1) fused QKV projections (2-term; Q hi-only, K hi/lo, V^T hi/lo)
    {
        dim3 grid(DIM / BN, M / BM, 3);
        qkv_gemm<<<grid, THREADS, SMEM_TOTAL>>>(xh,
                                                wqh, wql, wkh, wkl, wvh, wvl,
                                                bq, bk, bv,
                                                qh, kh, kl);
    }

    // 2) scores = (Qh @ (Kh+Kl)^T) / 32, causal tiles only, heavy-first
    {
        dim3 grid(SEQ / BN, SEQ / BM, BATCH);
        tc_gemm<<<grid, THREADS, SMEM_TOTAL>>>(qh, kh, kl, sp,
                                               DIM, DIM, DIM, SEQ, 0.03125f,
                                               F_CAUSAL_SKIP | F_REV_Y,
                                               sQK, sQK, sSS);
    }

    // 3) causal softmax -> hi-only fp16 P
    {
        dim3 grid(SEQ, BATCH);
        causal_softmax<<<grid, 256>>>(sp, ph, SEQ);
    }

    // 4) out = Ph @ (Vth+Vtl)^T  (causal K-limit, heavy-first)
    {
        dim3 grid(DIM / BN, SEQ / BM, BATCH);
        tc_gemm<<<grid, THREADS, SMEM_TOTAL>>>(ph, vth, vtl, out,
                                               SEQ, SEQ, SEQ, DIM, 1.0f,
                                               F_CAUSAL_KLIM | F_REV_Y,
                                               sSS, sVT, sQK);
    }
}

// round 16
// speedup vs baseline: 2.0644x; 1.2109x over previous
#include <cuda_runtime.h>
#include <cuda_fp16.h>
#include <cstdint>
#include <math.h>

// Problem constants
#define BATCH 4
#define SEQ   2048
#define DIM   1024

#define BM 128
#define BN 128
#define KC 64            // K elements (halfs) per stage (128B rows, SW128)
#define THREADS 512

// flags
#define F_CAUSAL_SKIP  1
#define F_CAUSAL_KLIM  2
#define F_REV_Y        32

#define NX (BATCH * SEQ * DIM)   // 8M
#define NW (DIM * DIM)           // 1M
#define NS (BATCH * SEQ * SEQ)   // 16M

#define TILE_B   (BM * KC * 2)   // 16384
// QKV kernel: 3 tiles (Ah,Bh,Bl) per stage
#define S3_OFF_BH  TILE_B
#define S3_OFF_BL  (2 * TILE_B)
#define STAGE3_B   (3 * TILE_B)          // 49152
#define SMEM3      (2 * STAGE3_B)        // 98304
// 1-term kernel: 2 tiles (A,B) per stage
#define S2_OFF_B   TILE_B
#define STAGE2_B   (2 * TILE_B)          // 32768
#define SMEM2      (2 * STAGE2_B)        // 65536

// Scratch (allocation-free)
__device__ __half g_xh[NX];
__device__ __half g_wqh[NW], g_wql[NW];
__device__ __half g_wkh[NW], g_wkl[NW];
__device__ __half g_wvh[NW], g_wvl[NW];
__device__ __half g_qh[NX];
__device__ __half g_kh[NX];
__device__ __half g_vth[NX];              // V transposed [b][d][s], hi only
__device__ float  g_s[NS];
__device__ __half g_ph[NS];               // P hi only

__device__ __forceinline__ uint32_t smem_u32(const void* p) {
    uint32_t a;
    asm("{ .reg .u64 t; cvta.to.shared.u64 t, %1; cvt.u32.u64 %0, t; }" : "=r"(a) : "l"(p));
    return a;
}

#define LDMATRIX_X4(r0, r1, r2, r3, addr)                                      \
    asm volatile("ldmatrix.sync.aligned.m8n8.x4.shared.b16 {%0,%1,%2,%3}, [%4];" \
        : "=r"(r0), "=r"(r1), "=r"(r2), "=r"(r3) : "r"(addr))

#define MMA16816(d0, d1, d2, d3, a0, a1, a2, a3, b0, b1)                       \
    asm volatile("mma.sync.aligned.m16n8k16.row.col.f32.f16.f16.f32 "          \
        "{%0,%1,%2,%3},{%4,%5,%6,%7},{%8,%9},{%0,%1,%2,%3};"                   \
        : "+f"(d0), "+f"(d1), "+f"(d2), "+f"(d3)                               \
        : "r"(a0), "r"(a1), "r"(a2), "r"(a3), "r"(b0), "r"(b1))

#define CP16(dst, src) \
    asm volatile("cp.async.cg.shared.global [%0], [%1], 16;" :: "r"(dst), "l"(src))
#define CP_COMMIT()  asm volatile("cp.async.commit_group;" ::: "memory")
#define CP_WAIT1()   asm volatile("cp.async.wait_group 1;" ::: "memory")
#define CP_WAIT0()   asm volatile("cp.async.wait_group 0;" ::: "memory")

// SW128 swizzle for 128-byte rows (KC=64 halfs)
__device__ __forceinline__ uint32_t sw128(uint32_t off) {
    return off ^ ((off >> 3) & 0x70);
}

// split fp32 -> fp16 hi + fp16 residual
__device__ __forceinline__ void split1(float x, __half& h, __half& l) {
    h = __float2half_rn(x);
    l = __float2half_rn(x - __half2float(h));
}

// ---------------------------------------------------------------------------
// Fused QKV projection: 2-term (X_h * (W_h + W_l)); grid (8, 64, 3).
// wsel 0 -> Q hi; 1 -> K hi; 2 -> V transposed hi.
// ---------------------------------------------------------------------------
__global__ void __launch_bounds__(THREADS, 1)
qkv_gemm(const __half* __restrict__ Xh,
         const __half* __restrict__ W0h, const __half* __restrict__ W0l,
         const __half* __restrict__ W1h, const __half* __restrict__ W1l,
         const __half* __restrict__ W2h, const __half* __restrict__ W2l,
         const float* __restrict__ b0, const float* __restrict__ b1,
         const float* __restrict__ b2,
         __half* __restrict__ Qh, __half* __restrict__ Kh)
{
    const int bx = blockIdx.x, by = blockIdx.y, wsel = blockIdx.z;

    extern __shared__ __align__(1024) char smem[];
    const uint32_t sbase = smem_u32(smem);

    const int tid  = threadIdx.x;
    const int lane = tid & 31;
    const int wid  = tid >> 5;
    const int wm   = wid & 3;
    const int wn   = wid >> 2;

    const int nkb = DIM / KC;

    const __half* pBh = wsel == 0 ? W0h : (wsel == 1 ? W1h : W2h);
    const __half* pBl = wsel == 0 ? W0l : (wsel == 1 ? W1l : W2l);
    const float*  bias = wsel == 0 ? b0 : (wsel == 1 ? b1 : b2);

    const __half* pAh = Xh + (size_t)by * BM * DIM;
    pBh += (size_t)bx * BN * DIM;
    pBl += (size_t)bx * BN * DIM;

    const int lrow = tid >> 2;
    const int lc   = (tid & 3) * 2;
    const uint32_t so0 = sw128(lrow * 128 + lc * 16);
    const uint32_t so1 = sw128(lrow * 128 + lc * 16 + 16);
    const size_t gA = (size_t)lrow * DIM + lc * 8;

    float acc[2][4][4];
#pragma unroll
    for (int i = 0; i < 2; i++)
#pragma unroll
        for (int j = 0; j < 4; j++)
#pragma unroll
            for (int c = 0; c < 4; c++) acc[i][j][c] = 0.0f;

    const int lr  = lane & 7;
    const int grp = lane >> 3;
    const int lm_row_off = lr + ((grp & 1) << 3);
    const int lm_col_off = (grp >> 1) << 4;

#define LOAD_STAGE3(buf, kb) do {                                              \
        const int _k0 = (kb) * KC;                                             \
        const uint32_t _sb = sbase + (buf) * STAGE3_B;                         \
        CP16(_sb + so0,             pAh + gA + _k0);                           \
        CP16(_sb + so1,             pAh + gA + _k0 + 8);                       \
        CP16(_sb + S3_OFF_BH + so0, pBh + gA - gA + (size_t)lrow * DIM + lc * 8 + _k0); \
        CP16(_sb + S3_OFF_BH + so1, pBh + (size_t)lrow * DIM + lc * 8 + _k0 + 8); \
        CP16(_sb + S3_OFF_BL + so0, pBl + (size_t)lrow * DIM + lc * 8 + _k0);  \
        CP16(_sb + S3_OFF_BL + so1, pBl + (size_t)lrow * DIM + lc * 8 + _k0 + 8); \
        CP_COMMIT();                                                           \
    } while (0)

    LOAD_STAGE3(0, 0);

    for (int kb = 0; kb < nkb; kb++) {
        const int buf = kb & 1;
        if (kb + 1 < nkb) { LOAD_STAGE3(buf ^ 1, kb + 1); CP_WAIT1(); }
        else              { CP_WAIT0(); }
        __syncthreads();

        const uint32_t uAh = sbase + buf * STAGE3_B;
        const uint32_t uBh = uAh + S3_OFF_BH;
        const uint32_t uBl = uAh + S3_OFF_BL;

#pragma unroll
        for (int ks = 0; ks < 4; ks++) {
            const uint32_t kbyte = ks * 32 + lm_col_off;

            uint32_t bh[2][4], bl[2][4];
#pragma unroll
            for (int ng = 0; ng < 2; ng++) {
                int nrow = wn * 32 + ng * 16 + lm_row_off;
                uint32_t off = sw128(nrow * 128 + kbyte);
                LDMATRIX_X4(bh[ng][0], bh[ng][1], bh[ng][2], bh[ng][3], uBh + off);
                LDMATRIX_X4(bl[ng][0], bl[ng][1], bl[ng][2], bl[ng][3], uBl + off);
            }

#pragma unroll
            for (int mt = 0; mt < 2; mt++) {
                int mrow = wm * 32 + mt * 16 + lm_row_off;
                uint32_t off = sw128(mrow * 128 + kbyte);
                uint32_t ah[4];
                LDMATRIX_X4(ah[0], ah[1], ah[2], ah[3], uAh + off);

#pragma unroll
                for (int nt = 0; nt < 4; nt++) {
                    const int ng = nt >> 1, s = nt & 1;
                    float* d = acc[mt][nt];
                    MMA16816(d[0], d[1], d[2], d[3],
                             ah[0], ah[1], ah[2], ah[3], bh[ng][s], bh[ng][s + 2]);
                    MMA16816(d[0], d[1], d[2], d[3],
                             ah[0], ah[1], ah[2], ah[3], bl[ng][s], bl[ng][s + 2]);
                }
            }
        }
        __syncthreads();
    }
#undef LOAD_STAGE3

    const int r0 = by * BM + wm * 32 + (lane >> 2);
    const int c0 = bx * BN + wn * 32 + ((lane & 3) << 1);

    if (wsel < 2) {
        // Q or K: hi only, row-major
        __half* Ch = wsel == 0 ? Qh : Kh;
#pragma unroll
        for (int mt = 0; mt < 2; mt++) {
#pragma unroll
            for (int nt = 0; nt < 4; nt++) {
                int row = r0 + mt * 16;
                int col = c0 + nt * 8;
                float b0f = bias[col], b1f = bias[col + 1];
                size_t o0 = (size_t)row * DIM + col;
                size_t o1 = o0 + 8ull * DIM;
                *(__half2*)(Ch + o0) = __floats2half2_rn(acc[mt][nt][0] + b0f,
                                                         acc[mt][nt][1] + b1f);
                *(__half2*)(Ch + o1) = __floats2half2_rn(acc[mt][nt][2] + b0f,
                                                         acc[mt][nt][3] + b1f);
            }
        }
    } else {
        // V -> transposed [b][d][s], hi only
#pragma unroll
        for (int mt = 0; mt < 2; mt++) {
            int row = r0 + mt * 16;
            int b = row >> 11;
            int s = row & (SEQ - 1);
            __half* dh = g_vth + (size_t)b * DIM * SEQ + s;
#pragma unroll
            for (int nt = 0; nt < 4; nt++) {
                int col = c0 + nt * 8;
                float b0f = bias[col], b1f = bias[col + 1];
                dh[(size_t)col * SEQ]           = __float2half_rn(acc[mt][nt][0] + b0f);
                dh[(size_t)(col + 1) * SEQ]     = __float2half_rn(acc[mt][nt][1] + b1f);
                dh[(size_t)col * SEQ + 8]       = __float2half_rn(acc[mt][nt][2] + b0f);
                dh[(size_t)(col + 1) * SEQ + 8] = __float2half_rn(acc[mt][nt][3] + b1f);
            }
        }
    }
}

// ---------------------------------------------------------------------------
// Pure-fp16 1-term NT GEMM (scores / PV): C = scale * (A @ B^T), fp32 out.
// ---------------------------------------------------------------------------
__global__ void __launch_bounds__(THREADS, 1)
tc_gemm(const __half* __restrict__ Ah_, const __half* __restrict__ Bh_,
        float* __restrict__ C,
        int K, int ldA, int ldB, int ldC, float scale, int flags,
        long long sA, long long sB, long long sC)
{
    const int bx = blockIdx.x, bz = blockIdx.z;
    int by = blockIdx.y;
    if (flags & F_REV_Y) by = gridDim.y - 1 - by;
    if ((flags & F_CAUSAL_SKIP) && bx > by) return;

    extern __shared__ __align__(1024) char smem[];
    const uint32_t sbase = smem_u32(smem);

    const int tid  = threadIdx.x;
    const int lane = tid & 31;
    const int wid  = tid >> 5;
    const int wm   = wid & 3;
    const int wn   = wid >> 2;

    int kend = K;
    if (flags & F_CAUSAL_KLIM) kend = min(K, (by + 1) * BM);
    const int nkb = kend / KC;

    const size_t aoff = (size_t)bz * sA + (size_t)by * BM * ldA;
    const size_t boff = (size_t)bz * sB + (size_t)bx * BN * ldB;
    const __half* pAh = Ah_ + aoff;
    const __half* pBh = Bh_ + boff;

    const int lrow = tid >> 2;
    const int lc   = (tid & 3) * 2;
    const uint32_t so0 = sw128(lrow * 128 + lc * 16);
    const uint32_t so1 = sw128(lrow * 128 + lc * 16 + 16);
    const size_t gA = (size_t)lrow * ldA + lc * 8;
    const size_t gB = (size_t)lrow * ldB + lc * 8;

    float acc[2][4][4];
#pragma unroll
    for (int i = 0; i < 2; i++)
#pragma unroll
        for (int j = 0; j < 4; j++)
#pragma unroll
            for (int c = 0; c < 4; c++) acc[i][j][c] = 0.0f;

    const int lr  = lane & 7;
    const int grp = lane >> 3;
    const int lm_row_off = lr + ((grp & 1) << 3);
    const int lm_col_off = (grp >> 1) << 4;

#define LOAD_STAGE2(buf, kb) do {                                              \
        const int _k0 = (kb) * KC;                                             \
        const uint32_t _sb = sbase + (buf) * STAGE2_B;                         \
        CP16(_sb + so0,            pAh + gA + _k0);                            \
        CP16(_sb + so1,            pAh + gA + _k0 + 8);                        \
        CP16(_sb + S2_OFF_B + so0, pBh + gB + _k0);                            \
        CP16(_sb + S2_OFF_B + so1, pBh + gB + _k0 + 8);                        \
        CP_COMMIT();                                                           \
    } while (0)

    LOAD_STAGE2(0, 0);

    for (int kb = 0; kb < nkb; kb++) {
        const int buf = kb & 1;
        if (kb + 1 < nkb) { LOAD_STAGE2(buf ^ 1, kb + 1); CP_WAIT1(); }
        else              { CP_WAIT0(); }
        __syncthreads();

        const uint32_t uAh = sbase + buf * STAGE2_B;
        const uint32_t uBh = uAh + S2_OFF_B;

#pragma unroll
        for (int ks = 0; ks < 4; ks++) {
            const uint32_t kbyte = ks * 32 + lm_col_off;

            uint32_t bh[2][4];
#pragma unroll
            for (int ng = 0; ng < 2; ng++) {
                int nrow = wn * 32 + ng * 16 + lm_row_off;
                uint32_t off = sw128(nrow * 128 + kbyte);
                LDMATRIX_X4(bh[ng][0], bh[ng][1], bh[ng][2], bh[ng][3], uBh + off);
            }

#pragma unroll
            for (int mt = 0; mt < 2; mt++) {
                int mrow = wm * 32 + mt * 16 + lm_row_off;
                uint32_t off = sw128(mrow * 128 + kbyte);
                uint32_t ah[4];
                LDMATRIX_X4(ah[0], ah[1], ah[2], ah[3], uAh + off);

#pragma unroll
                for (int nt = 0; nt < 4; nt++) {
                    const int ng = nt >> 1, s = nt & 1;
                    float* d = acc[mt][nt];
                    MMA16816(d[0], d[1], d[2], d[3],
                             ah[0], ah[1], ah[2], ah[3], bh[ng][s], bh[ng][s + 2]);
                }
            }
        }
        __syncthreads();
    }
#undef LOAD_STAGE2

    const int r0 = by * BM + wm * 32 + (lane >> 2);
    const int c0 = bx * BN + wn * 32 + ((lane & 3) << 1);

#pragma unroll
    for (int mt = 0; mt < 2; mt++) {
#pragma unroll
        for (int nt = 0; nt < 4; nt++) {
            int row = r0 + mt * 16;
            int col = c0 + nt * 8;
            float* dst = C + (size_t)bz * sC + (size_t)row * ldC + col;
            *(float2*)dst = make_float2(acc[mt][nt][0] * scale,
                                        acc[mt][nt][1] * scale);
            *(float2*)(dst + 8ull * ldC) = make_float2(acc[mt][nt][2] * scale,
                                                       acc[mt][nt][3] * scale);
        }
    }
}

// ---------------------------------------------------------------------------
// fp32 -> hi-only fp16
__global__ void __launch_bounds__(256)
split_hi(const float* __restrict__ x, __half* __restrict__ h, int n4)
{
    int i = blockIdx.x * blockDim.x + threadIdx.x;
    if (i >= n4) return;
    float4 v = ((const float4*)x)[i];
    ((__half2*)h)[i * 2]     = __floats2half2_rn(v.x, v.y);
    ((__half2*)h)[i * 2 + 1] = __floats2half2_rn(v.z, v.w);
}

// fp32 -> (hi, lo) fp16 split
__global__ void __launch_bounds__(256)
split_f32(const float* __restrict__ x, __half* __restrict__ h,
          __half* __restrict__ l, int n4)
{
    int i = blockIdx.x * blockDim.x + threadIdx.x;
    if (i >= n4) return;
    float4 v = ((const float4*)x)[i];
    __half hx = __float2half_rn(v.x), hy = __float2half_rn(v.y);
    __half hz = __float2half_rn(v.z), hw = __float2half_rn(v.w);
    ((__half2*)h)[i * 2]     = __halves2half2(hx, hy);
    ((__half2*)h)[i * 2 + 1] = __halves2half2(hz, hw);
    ((__half2*)l)[i * 2]     = __floats2half2_rn(v.x - __half2float(hx), v.y - __half2float(hy));
    ((__half2*)l)[i * 2 + 1] = __floats2half2_rn(v.z - __half2float(hz), v.w - __half2float(hw));
}

// ---------------------------------------------------------------------------
// Causal row softmax: fp32 scores -> hi-only fp16 probabilities (zero tails)
// ---------------------------------------------------------------------------
__global__ void __launch_bounds__(256)
causal_softmax(const float* __restrict__ S, __half* __restrict__ Ph, int seq)
{
    int r = blockIdx.x;
    int b = blockIdx.y;
    size_t base = ((size_t)b * seq + (size_t)r) * seq;
    const float* row = S + base;
    int n = r + 1;
    int tid = threadIdx.x;

    __shared__ float red[256];

    float m = -1e30f;
    for (int j = tid; j < n; j += 256) m = fmaxf(m, row[j]);
    red[tid] = m; __syncthreads();
    for (int s = 128; s > 0; s >>= 1) {
        if (tid < s) red[tid] = fmaxf(red[tid], red[tid + s]);
        __syncthreads();
    }
    m = red[0]; __syncthreads();

    float ev[8];
    int cnt = 0;
    float sum = 0.0f;
    for (int j = tid; j < n; j += 256) {
        float e = __expf(row[j] - m);
        ev[cnt++] = e;
        sum += e;
    }
    red[tid] = sum; __syncthreads();
    for (int s = 128; s > 0; s >>= 1) {
        if (tid < s) red[tid] += red[tid + s];
        __syncthreads();
    }
    float inv = 1.0f / red[0];

    cnt = 0;
    for (int j = tid; j < n; j += 256)
        Ph[base + j] = __float2half_rn(ev[cnt++] * inv);
    __half z = __float2half_rn(0.0f);
    for (int j = n + tid; j < seq; j += 256)
        Ph[base + j] = z;
}

// ---------------------------------------------------------------------------
extern "C" void kernel_launch(void* const* d_in, const int* in_sizes, int n_in,
                              void* d_out, int out_size)
{
    const float* X  = (const float*)d_in[0];
    const float* Wq = (const float*)d_in[1];
    const float* bq = (const float*)d_in[2];
    const float* Wk = (const float*)d_in[3];
    const float* bk = (const float*)d_in[4];
    const float* Wv = (const float*)d_in[5];
    const float* bv = (const float*)d_in[6];
    float* out = (float*)d_out;

    __half *xh, *wqh, *wql, *wkh, *wkl, *wvh, *wvl;
    __half *qh, *kh, *vth, *ph;
    float* sp;
    cudaGetSymbolAddress((void**)&xh,  g_xh);
    cudaGetSymbolAddress((void**)&wqh, g_wqh); cudaGetSymbolAddress((void**)&wql, g_wql);
    cudaGetSymbolAddress((void**)&wkh, g_wkh); cudaGetSymbolAddress((void**)&wkl, g_wkl);
    cudaGetSymbolAddress((void**)&wvh, g_wvh); cudaGetSymbolAddress((void**)&wvl, g_wvl);
    cudaGetSymbolAddress((void**)&qh,  g_qh);
    cudaGetSymbolAddress((void**)&kh,  g_kh);
    cudaGetSymbolAddress((void**)&vth, g_vth);
    cudaGetSymbolAddress((void**)&ph,  g_ph);
    cudaGetSymbolAddress((void**)&sp,  g_s);

    static int smem_set = 0;
    if (!smem_set) {
        cudaFuncSetAttribute(tc_gemm,  cudaFuncAttributeMaxDynamicSharedMemorySize, SMEM2);
        cudaFuncSetAttribute(qkv_gemm, cudaFuncAttributeMaxDynamicSharedMemorySize, SMEM3);
        smem_set = 1;
    }

    const int M = BATCH * SEQ;                       // 8192
    const long long sQK = (long long)SEQ * DIM;
    const long long sVT = (long long)DIM * SEQ;
    const long long sSS = (long long)SEQ * SEQ;

    // 0) pre-split: X hi-only; weights hi/lo
    split_hi <<<(NX / 4 + 255) / 256, 256>>>(X,  xh,  NX / 4);
    split_f32<<<(NW / 4 + 255) / 256, 256>>>(Wq, wqh, wql, NW / 4);
    split_f32<<<(NW / 4 + 255) / 256, 256>>>(Wk, wkh, wkl, NW / 4);
    split_f32<<<(NW / 4 + 255) / 256, 256>>>(Wv, wvh, wvl, NW / 4);

    // 1) fused QKV projections (2-term; Q/K hi, V^T hi)
    {
        dim3 grid(DIM / BN, M / BM, 3);
        qkv_gemm<<<grid, THREADS, SMEM3>>>(xh,
                                           wqh, wql, wkh, wkl, wvh, wvl,
                                           bq, bk, bv,
                                           qh, kh);
    }

    // 2) scores = (Qh @ Kh^T) / 32, pure fp16, causal tiles only, heavy-first
    {
        dim3 grid(SEQ / BN, SEQ / BM, BATCH);
        tc_gemm<<<grid, THREADS, SMEM2>>>(qh, kh, sp,
                                          DIM, DIM, DIM, SEQ, 0.03125f,
                                          F_CAUSAL_SKIP | F_REV_Y,
                                          sQK, sQK, sSS);
    }

    // 3) causal softmax -> hi-only fp16 P
    {
        dim3 grid(SEQ, BATCH);
        causal_softmax<<<grid, 256>>>(sp, ph, SEQ);
    }

    // 4) out = Ph @ Vth^T, pure fp16 (causal K-limit, heavy-first)
    {
        dim3 grid(DIM / BN, SEQ / BM, BATCH);
        tc_gemm<<<grid, THREADS, SMEM2>>>(ph, vth, out,
                                          SEQ, SEQ, SEQ, DIM, 1.0f,
                                          F_CAUSAL_KLIM | F_REV_Y,
                                          sSS, sVT, sQK);
    }
}

// round 17
// speedup vs baseline: 2.8077x; 1.3601x over previous
#include <cuda_runtime.h>
#include <cuda_fp16.h>
#include <cstdint>
#include <math.h>

// Problem constants
#define BATCH 4
#define SEQ   2048
#define DIM   1024

#define BM 128
#define BN 128
#define KC 64            // K elements (halfs) per stage (128B rows, SW128)
#define THREADS 512

// flags
#define F_CAUSAL_SKIP  1
#define F_CAUSAL_KLIM  2
#define F_REV_Y        32

#define NX (BATCH * SEQ * DIM)   // 8M
#define NW (DIM * DIM)           // 1M
#define NS (BATCH * SEQ * SEQ)   // 16M

#define TILE_B   (BM * KC * 2)   // 16384
#define S2_OFF_B   TILE_B
#define STAGE2_B   (2 * TILE_B)          // 32768
#define SMEM2      (2 * STAGE2_B)        // 65536

// Scratch (allocation-free) — all pure fp16 now
__device__ __half g_xh[NX];
__device__ __half g_wqh[NW];
__device__ __half g_wkh[NW];
__device__ __half g_wvh[NW];
__device__ __half g_qh[NX];
__device__ __half g_kh[NX];
__device__ __half g_vth[NX];              // V transposed [b][d][s]
__device__ float  g_s[NS];
__device__ __half g_ph[NS];

__device__ __forceinline__ uint32_t smem_u32(const void* p) {
    uint32_t a;
    asm("{ .reg .u64 t; cvta.to.shared.u64 t, %1; cvt.u32.u64 %0, t; }" : "=r"(a) : "l"(p));
    return a;
}

#define LDMATRIX_X4(r0, r1, r2, r3, addr)                                      \
    asm volatile("ldmatrix.sync.aligned.m8n8.x4.shared.b16 {%0,%1,%2,%3}, [%4];" \
        : "=r"(r0), "=r"(r1), "=r"(r2), "=r"(r3) : "r"(addr))

#define MMA16816(d0, d1, d2, d3, a0, a1, a2, a3, b0, b1)                       \
    asm volatile("mma.sync.aligned.m16n8k16.row.col.f32.f16.f16.f32 "          \
        "{%0,%1,%2,%3},{%4,%5,%6,%7},{%8,%9},{%0,%1,%2,%3};"                   \
        : "+f"(d0), "+f"(d1), "+f"(d2), "+f"(d3)                               \
        : "r"(a0), "r"(a1), "r"(a2), "r"(a3), "r"(b0), "r"(b1))

#define CP16(dst, src) \
    asm volatile("cp.async.cg.shared.global [%0], [%1], 16;" :: "r"(dst), "l"(src))
#define CP_COMMIT()  asm volatile("cp.async.commit_group;" ::: "memory")
#define CP_WAIT1()   asm volatile("cp.async.wait_group 1;" ::: "memory")
#define CP_WAIT0()   asm volatile("cp.async.wait_group 0;" ::: "memory")

// SW128 swizzle for 128-byte rows (KC=64 halfs)
__device__ __forceinline__ uint32_t sw128(uint32_t off) {
    return off ^ ((off >> 3) & 0x70);
}

// ---------------------------------------------------------------------------
// Shared 1-term fp16 mainloop (pure fp16 operands, fp32 accum).
// Requires in scope: sbase, pAh, pBh, gA, gB, so0, so1, nkb, acc,
// lm_row_off, lm_col_off, wm, wn.
// ---------------------------------------------------------------------------
#define LOAD_STAGE2(buf, kb) do {                                              \
        const int _k0 = (kb) * KC;                                             \
        const uint32_t _sb = sbase + (buf) * STAGE2_B;                         \
        CP16(_sb + so0,            pAh + gA + _k0);                            \
        CP16(_sb + so1,            pAh + gA + _k0 + 8);                        \
        CP16(_sb + S2_OFF_B + so0, pBh + gB + _k0);                            \
        CP16(_sb + S2_OFF_B + so1, pBh + gB + _k0 + 8);                        \
        CP_COMMIT();                                                           \
    } while (0)

#define GEMM_MAINLOOP1()                                                       \
    LOAD_STAGE2(0, 0);                                                         \
    for (int kb = 0; kb < nkb; kb++) {                                         \
        const int buf = kb & 1;                                                \
        if (kb + 1 < nkb) { LOAD_STAGE2(buf ^ 1, kb + 1); CP_WAIT1(); }        \
        else              { CP_WAIT0(); }                                      \
        __syncthreads();                                                       \
        const uint32_t uAh = sbase + buf * STAGE2_B;                           \
        const uint32_t uBh = uAh + S2_OFF_B;                                   \
        _Pragma("unroll")                                                      \
        for (int ks = 0; ks < 4; ks++) {                                       \
            const uint32_t kbyte = ks * 32 + lm_col_off;                       \
            uint32_t bh[2][4];                                                 \
            _Pragma("unroll")                                                  \
            for (int ng = 0; ng < 2; ng++) {                                   \
                int nrow = wn * 32 + ng * 16 + lm_row_off;                     \
                uint32_t off = sw128(nrow * 128 + kbyte);                      \
                LDMATRIX_X4(bh[ng][0], bh[ng][1], bh[ng][2], bh[ng][3], uBh + off); \
            }                                                                  \
            _Pragma("unroll")                                                  \
            for (int mt = 0; mt < 2; mt++) {                                   \
                int mrow = wm * 32 + mt * 16 + lm_row_off;                     \
                uint32_t off = sw128(mrow * 128 + kbyte);                      \
                uint32_t ah[4];                                                \
                LDMATRIX_X4(ah[0], ah[1], ah[2], ah[3], uAh + off);            \
                _Pragma("unroll")                                              \
                for (int nt = 0; nt < 4; nt++) {                               \
                    const int ng = nt >> 1, s = nt & 1;                        \
                    float* d = acc[mt][nt];                                    \
                    MMA16816(d[0], d[1], d[2], d[3],                           \
                             ah[0], ah[1], ah[2], ah[3], bh[ng][s], bh[ng][s + 2]); \
                }                                                              \
            }                                                                  \
        }                                                                      \
        __syncthreads();                                                       \
    }

// ---------------------------------------------------------------------------
// Fused QKV projection, pure fp16 1-term: grid (8, 64, 3).
// wsel 0 -> Q hi; 1 -> K hi; 2 -> V transposed hi.
// ---------------------------------------------------------------------------
__global__ void __launch_bounds__(THREADS, 1)
qkv_gemm(const __half* __restrict__ Xh,
         const __half* __restrict__ W0h, const __half* __restrict__ W1h,
         const __half* __restrict__ W2h,
         const float* __restrict__ b0, const float* __restrict__ b1,
         const float* __restrict__ b2,
         __half* __restrict__ Qh, __half* __restrict__ Kh)
{
    const int bx = blockIdx.x, by = blockIdx.y, wsel = blockIdx.z;

    extern __shared__ __align__(1024) char smem[];
    const uint32_t sbase = smem_u32(smem);

    const int tid  = threadIdx.x;
    const int lane = tid & 31;
    const int wid  = tid >> 5;
    const int wm   = wid & 3;
    const int wn   = wid >> 2;

    const int nkb = DIM / KC;

    const __half* pBh = wsel == 0 ? W0h : (wsel == 1 ? W1h : W2h);
    const float*  bias = wsel == 0 ? b0 : (wsel == 1 ? b1 : b2);

    const __half* pAh = Xh + (size_t)by * BM * DIM;
    pBh += (size_t)bx * BN * DIM;

    const int lrow = tid >> 2;
    const int lc   = (tid & 3) * 2;
    const uint32_t so0 = sw128(lrow * 128 + lc * 16);
    const uint32_t so1 = sw128(lrow * 128 + lc * 16 + 16);
    const size_t gA = (size_t)lrow * DIM + lc * 8;
    const size_t gB = (size_t)lrow * DIM + lc * 8;

    float acc[2][4][4];
#pragma unroll
    for (int i = 0; i < 2; i++)
#pragma unroll
        for (int j = 0; j < 4; j++)
#pragma unroll
            for (int c = 0; c < 4; c++) acc[i][j][c] = 0.0f;

    const int lr  = lane & 7;
    const int grp = lane >> 3;
    const int lm_row_off = lr + ((grp & 1) << 3);
    const int lm_col_off = (grp >> 1) << 4;

    GEMM_MAINLOOP1();

    const int r0 = by * BM + wm * 32 + (lane >> 2);
    const int c0 = bx * BN + wn * 32 + ((lane & 3) << 1);

    if (wsel < 2) {
        __half* Ch = wsel == 0 ? Qh : Kh;
#pragma unroll
        for (int mt = 0; mt < 2; mt++) {
#pragma unroll
            for (int nt = 0; nt < 4; nt++) {
                int row = r0 + mt * 16;
                int col = c0 + nt * 8;
                float b0f = bias[col], b1f = bias[col + 1];
                size_t o0 = (size_t)row * DIM + col;
                size_t o1 = o0 + 8ull * DIM;
                *(__half2*)(Ch + o0) = __floats2half2_rn(acc[mt][nt][0] + b0f,
                                                         acc[mt][nt][1] + b1f);
                *(__half2*)(Ch + o1) = __floats2half2_rn(acc[mt][nt][2] + b0f,
                                                         acc[mt][nt][3] + b1f);
            }
        }
    } else {
        // V -> transposed [b][d][s]
#pragma unroll
        for (int mt = 0; mt < 2; mt++) {
            int row = r0 + mt * 16;
            int b = row >> 11;
            int s = row & (SEQ - 1);
            __half* dh = g_vth + (size_t)b * DIM * SEQ + s;
#pragma unroll
            for (int nt = 0; nt < 4; nt++) {
                int col = c0 + nt * 8;
                float b0f = bias[col], b1f = bias[col + 1];
                dh[(size_t)col * SEQ]           = __float2half_rn(acc[mt][nt][0] + b0f);
                dh[(size_t)(col + 1) * SEQ]     = __float2half_rn(acc[mt][nt][1] + b1f);
                dh[(size_t)col * SEQ + 8]       = __float2half_rn(acc[mt][nt][2] + b0f);
                dh[(size_t)(col + 1) * SEQ + 8] = __float2half_rn(acc[mt][nt][3] + b1f);
            }
        }
    }
}

// ---------------------------------------------------------------------------
// Pure-fp16 1-term NT GEMM (scores / PV): C = scale * (A @ B^T), fp32 out.
// ---------------------------------------------------------------------------
__global__ void __launch_bounds__(THREADS, 1)
tc_gemm(const __half* __restrict__ Ah_, const __half* __restrict__ Bh_,
        float* __restrict__ C,
        int K, int ldA, int ldB, int ldC, float scale, int flags,
        long long sA, long long sB, long long sC)
{
    const int bx = blockIdx.x, bz = blockIdx.z;
    int by = blockIdx.y;
    if (flags & F_REV_Y) by = gridDim.y - 1 - by;
    if ((flags & F_CAUSAL_SKIP) && bx > by) return;

    extern __shared__ __align__(1024) char smem[];
    const uint32_t sbase = smem_u32(smem);

    const int tid  = threadIdx.x;
    const int lane = tid & 31;
    const int wid  = tid >> 5;
    const int wm   = wid & 3;
    const int wn   = wid >> 2;

    int kend = K;
    if (flags & F_CAUSAL_KLIM) kend = min(K, (by + 1) * BM);
    const int nkb = kend / KC;

    const size_t aoff = (size_t)bz * sA + (size_t)by * BM * ldA;
    const size_t boff = (size_t)bz * sB + (size_t)bx * BN * ldB;
    const __half* pAh = Ah_ + aoff;
    const __half* pBh = Bh_ + boff;

    const int lrow = tid >> 2;
    const int lc   = (tid & 3) * 2;
    const uint32_t so0 = sw128(lrow * 128 + lc * 16);
    const uint32_t so1 = sw128(lrow * 128 + lc * 16 + 16);
    const size_t gA = (size_t)lrow * ldA + lc * 8;
    const size_t gB = (size_t)lrow * ldB + lc * 8;

    float acc[2][4][4];
#pragma unroll
    for (int i = 0; i < 2; i++)
#pragma unroll
        for (int j = 0; j < 4; j++)
#pragma unroll
            for (int c = 0; c < 4; c++) acc[i][j][c] = 0.0f;

    const int lr  = lane & 7;
    const int grp = lane >> 3;
    const int lm_row_off = lr + ((grp & 1) << 3);
    const int lm_col_off = (grp >> 1) << 4;

    GEMM_MAINLOOP1();

    const int r0 = by * BM + wm * 32 + (lane >> 2);
    const int c0 = bx * BN + wn * 32 + ((lane & 3) << 1);

#pragma unroll
    for (int mt = 0; mt < 2; mt++) {
#pragma unroll
        for (int nt = 0; nt < 4; nt++) {
            int row = r0 + mt * 16;
            int col = c0 + nt * 8;
            float* dst = C + (size_t)bz * sC + (size_t)row * ldC + col;
            *(float2*)dst = make_float2(acc[mt][nt][0] * scale,
                                        acc[mt][nt][1] * scale);
            *(float2*)(dst + 8ull * ldC) = make_float2(acc[mt][nt][2] * scale,
                                                       acc[mt][nt][3] * scale);
        }
    }
}

// ---------------------------------------------------------------------------
// fp32 -> hi-only fp16
__global__ void __launch_bounds__(256)
split_hi(const float* __restrict__ x, __half* __restrict__ h, int n4)
{
    int i = blockIdx.x * blockDim.x + threadIdx.x;
    if (i >= n4) return;
    float4 v = ((const float4*)x)[i];
    ((__half2*)h)[i * 2]     = __floats2half2_rn(v.x, v.y);
    ((__half2*)h)[i * 2 + 1] = __floats2half2_rn(v.z, v.w);
}

// ---------------------------------------------------------------------------
// Causal row softmax: fp32 scores -> hi-only fp16 probabilities (zero tails)
// ---------------------------------------------------------------------------
__global__ void __launch_bounds__(256)
causal_softmax(const float* __restrict__ S, __half* __restrict__ Ph, int seq)
{
    int r = blockIdx.x;
    int b = blockIdx.y;
    size_t base = ((size_t)b * seq + (size_t)r) * seq;
    const float* row = S + base;
    int n = r + 1;
    int tid = threadIdx.x;

    __shared__ float red[256];

    float m = -1e30f;
    for (int j = tid; j < n; j += 256) m = fmaxf(m, row[j]);
    red[tid] = m; __syncthreads();
    for (int s = 128; s > 0; s >>= 1) {
        if (tid < s) red[tid] = fmaxf(red[tid], red[tid + s]);
        __syncthreads();
    }
    m = red[0]; __syncthreads();

    float ev[8];
    int cnt = 0;
    float sum = 0.0f;
    for (int j = tid; j < n; j += 256) {
        float e = __expf(row[j] - m);
        ev[cnt++] = e;
        sum += e;
    }
    red[tid] = sum; __syncthreads();
    for (int s = 128; s > 0; s >>= 1) {
        if (tid < s) red[tid] += red[tid + s];
        __syncthreads();
    }
    float inv = 1.0f / red[0];

    cnt = 0;
    for (int j = tid; j < n; j += 256)
        Ph[base + j] = __float2half_rn(ev[cnt++] * inv);
    __half z = __float2half_rn(0.0f);
    for (int j = n + tid; j < seq; j += 256)
        Ph[base + j] = z;
}

// ---------------------------------------------------------------------------
extern "C" void kernel_launch(void* const* d_in, const int* in_sizes, int n_in,
                              void* d_out, int out_size)
{
    const float* X  = (const float*)d_in[0];
    const float* Wq = (const float*)d_in[1];
    const float* bq = (const float*)d_in[2];
    const float* Wk = (const float*)d_in[3];
    const float* bk = (const float*)d_in[4];
    const float* Wv = (const float*)d_in[5];
    const float* bv = (const float*)d_in[6];
    float* out = (float*)d_out;

    __half *xh, *wqh, *wkh, *wvh, *qh, *kh, *vth, *ph;
    float* sp;
    cudaGetSymbolAddress((void**)&xh,  g_xh);
    cudaGetSymbolAddress((void**)&wqh, g_wqh);
    cudaGetSymbolAddress((void**)&wkh, g_wkh);
    cudaGetSymbolAddress((void**)&wvh, g_wvh);
    cudaGetSymbolAddress((void**)&qh,  g_qh);
    cudaGetSymbolAddress((void**)&kh,  g_kh);
    cudaGetSymbolAddress((void**)&vth, g_vth);
    cudaGetSymbolAddress((void**)&ph,  g_ph);
    cudaGetSymbolAddress((void**)&sp,  g_s);

    static int smem_set = 0;
    if (!smem_set) {
        cudaFuncSetAttribute(tc_gemm,  cudaFuncAttributeMaxDynamicSharedMemorySize, SMEM2);
        cudaFuncSetAttribute(qkv_gemm, cudaFuncAttributeMaxDynamicSharedMemorySize, SMEM2);
        smem_set = 1;
    }

    const int M = BATCH * SEQ;                       // 8192
    const long long sQK = (long long)SEQ * DIM;
    const long long sVT = (long long)DIM * SEQ;
    const long long sSS = (long long)SEQ * SEQ;

    // 0) pre-split: everything hi-only fp16
    split_hi<<<(NX / 4 + 255) / 256, 256>>>(X,  xh,  NX / 4);
    split_hi<<<(NW / 4 + 255) / 256, 256>>>(Wq, wqh, NW / 4);
    split_hi<<<(NW / 4 + 255) / 256, 256>>>(Wk, wkh, NW / 4);
    split_hi<<<(NW / 4 + 255) / 256, 256>>>(Wv, wvh, NW / 4);

    // 1) fused QKV projections (pure fp16 1-term; Q/K row-major, V transposed)
    {
        dim3 grid(DIM / BN, M / BM, 3);
        qkv_gemm<<<grid, THREADS, SMEM2>>>(xh, wqh, wkh, wvh,
                                           bq, bk, bv, qh, kh);
    }

    // 2) scores = (Qh @ Kh^T) / 32, causal tiles only, heavy-first
    {
        dim3 grid(SEQ / BN, SEQ / BM, BATCH);
        tc_gemm<<<grid, THREADS, SMEM2>>>(qh, kh, sp,
                                          DIM, DIM, DIM, SEQ, 0.03125f,
                                          F_CAUSAL_SKIP | F_REV_Y,
                                          sQK, sQK, sSS);
    }

    // 3) causal softmax -> hi-only fp16 P
    {
        dim3 grid(SEQ, BATCH);
        causal_softmax<<<grid, 256>>>(sp, ph, SEQ);
    }

    // 4) out = Ph @ Vth^T  (causal K-limit, heavy-first)
    {
        dim3 grid(DIM / BN, SEQ / BM, BATCH);
        tc_gemm<<<grid, THREADS, SMEM2>>>(ph, vth, out,
                                          SEQ, SEQ, SEQ, DIM, 1.0f,
                                          F_CAUSAL_KLIM | F_REV_Y,
                                          sSS, sVT, sQK);
    }
}